// round 13
// baseline (speedup 1.0000x reference)
#include <cuda_runtime.h>
#include <cuda_fp16.h>
#include <cstddef>
#include <cstdint>

// ---------------- problem constants ----------------
constexpr int kMaxN  = 50016;
constexpr int kMaxE  = 400000;
constexpr int kMaxTE = kMaxN + kMaxE;
constexpr int kHC1   = 256;
constexpr int kC2    = 64;

// ---------------- device scratch ----------------
__device__ __half g_xl1[(size_t)kMaxN * kHC1];
__device__ float  g_xr1[(size_t)kMaxN * kHC1];
__device__ __half g_h  [(size_t)kMaxN * kHC1];
__device__ __half g_xl2[(size_t)kMaxN * kC2];
__device__ float  g_xr2[(size_t)kMaxN * kC2];
__device__ int    g_deg[kMaxN];                 // zero-init at load; re-zeroed at graph end
__device__ int    g_off[kMaxN + 1];
__device__ int    g_cur[kMaxN];
__device__ int    g_bsum[128];
__device__ int    g_csr_src[kMaxTE];

// ---------------- small utility kernels ----------------
__global__ void zeroi(int* p, int n) {
    int i = blockIdx.x * blockDim.x + threadIdx.x;
    if (i < n) p[i] = 0;
}

__global__ void count_deg(const int* __restrict__ ei, int E, int TE, int* __restrict__ deg) {
    int i = blockIdx.x * blockDim.x + threadIdx.x;
    if (i >= TE) return;
    int d = (i < E) ? ei[E + i] : (i - E);
    atomicAdd(&deg[d], 1);
}

__global__ void scan_block(const int* __restrict__ deg, int* __restrict__ off,
                           int* __restrict__ bsum, int n) {
    __shared__ int sh[1024];
    int tid = threadIdx.x;
    int i = blockIdx.x * 1024 + tid;
    int v = (i < n) ? deg[i] : 0;
    sh[tid] = v;
    __syncthreads();
    for (int o = 1; o < 1024; o <<= 1) {
        int t = (tid >= o) ? sh[tid - o] : 0;
        __syncthreads();
        sh[tid] += t;
        __syncthreads();
    }
    if (i < n) off[i] = sh[tid] - v;
    if (tid == 1023) bsum[blockIdx.x] = sh[1023];
}

__global__ void scan_add2(int* __restrict__ off, const int* __restrict__ bsum,
                          int* __restrict__ cur, int n, int total, int nb) {
    __shared__ int sh[128];
    int tid = threadIdx.x;
    if (tid < 128) sh[tid] = (tid < nb) ? bsum[tid] : 0;
    __syncthreads();
    for (int o = 1; o < 128; o <<= 1) {
        int u = (tid >= o && tid < 128) ? sh[tid - o] : 0;
        __syncthreads();
        if (tid < 128) sh[tid] += u;
        __syncthreads();
    }
    int i = blockIdx.x * blockDim.x + tid;
    if (i < n) {
        int b = i >> 10;
        int add = (b == 0) ? 0 : sh[b - 1];
        int v = off[i] + add;
        off[i] = v;
        cur[i] = v;
    }
    if (i == 0) off[n] = total;
}

__global__ void scatter_csr(const int* __restrict__ ei, int E, int TE,
                            int* __restrict__ cur, int* __restrict__ csr_src) {
    int i = blockIdx.x * blockDim.x + threadIdx.x;
    if (i >= TE) return;
    int s, d;
    if (i < E) { s = ei[i]; d = ei[E + i]; }
    else       { s = i - E; d = s; }
    int pos = atomicAdd(&cur[d], 1);
    csr_src[pos] = s;
}

// ---------------- FP16 tensor-core dual-output GEMM ----------------
// C = A[MxK] @ [B1|B2] + bias, fp32 accumulate, operands fp16 in smem.
// Block 128x128, k-chunk 32, 8 warps (4M x 2N), warp tile 32x64.
// mma.m16n8k16.row.col.f32.f16.f16.f32; B fragments via ldmatrix.x2.trans.

__device__ __forceinline__ unsigned pack_h2(float a, float b) {
    __half2 h = __floats2half2_rn(a, b);
    return *(unsigned*)&h;
}

__device__ __forceinline__ void mma_f16(float* d, const unsigned* a, unsigned b0, unsigned b1) {
    asm volatile(
        "mma.sync.aligned.m16n8k16.row.col.f32.f16.f16.f32 "
        "{%0,%1,%2,%3}, {%4,%5,%6,%7}, {%8,%9}, {%0,%1,%2,%3};"
        : "+f"(d[0]), "+f"(d[1]), "+f"(d[2]), "+f"(d[3])
        : "r"(a[0]), "r"(a[1]), "r"(a[2]), "r"(a[3]), "r"(b0), "r"(b1));
}

constexpr int kBStrW = 68;   // Bs row stride in 32-bit words (64 + 4 pad)

// TA = float or __half for the A operand
template <typename TA, bool HALF1>
__global__ __launch_bounds__(256)
void gemm_dual_tc(const TA* __restrict__ A,
                  const float* __restrict__ B1, const float* __restrict__ bias1,
                  void* __restrict__ Cd1, int n1,
                  const float* __restrict__ B2, const float* __restrict__ bias2,
                  float* __restrict__ Cd2, int n2,
                  int M, int K) {
    // As: [128 m][16 half2-words] with 4-word chunk XOR swizzle (chunk ^ ((r>>1)&3))
    // Bs: [32 k][64 half2-words + 4 pad] plain layout for ldmatrix
    __shared__ unsigned AsW[128 * 16];
    __shared__ unsigned BsW[32 * kBStrW];

    const int tid  = threadIdx.x;
    const int lane = tid & 31;
    const int wid  = tid >> 5;
    const int wm   = (wid & 3) * 32;
    const int wn   = (wid >> 2) * 64;
    const int row0 = blockIdx.y * 128;
    const int col0 = blockIdx.x * 128;
    const int gr   = lane >> 2;
    const int kkw  = lane & 3;
    const int swz  = (gr >> 1) & 3;

    float d[2][8][4];
#pragma unroll
    for (int mi = 0; mi < 2; ++mi)
#pragma unroll
        for (int ni = 0; ni < 8; ++ni)
#pragma unroll
            for (int r = 0; r < 4; ++r) d[mi][ni][r] = 0.f;

    const int a_row = tid >> 2;        // 0..63
    const int a_k8  = (tid & 3) * 8;   // half index within the 32-k chunk
    const int b_k   = tid >> 5;        // 0..7
    const int b_n4  = (tid & 31) * 4;

    const uint32_t bSm = (uint32_t)__cvta_generic_to_shared(BsW);
    const uint32_t bLaneBase = bSm + (uint32_t)((((lane & 15) * kBStrW) + (wn >> 1)) * 4);

    const unsigned* Arow = AsW + (wm + gr) * 16;   // rows +128w(+8m), +256w(+16m), +384w(+24m)

    for (int k0 = 0; k0 < K; k0 += 32) {
        // ---- A tile (128 x 32) -> fp16 smem ----
#pragma unroll
        for (int p = 0; p < 2; ++p) {
            int r = p * 64 + a_row;
            uint4 w = make_uint4(0u, 0u, 0u, 0u);
            if (row0 + r < M) {
                if constexpr (sizeof(TA) == 4) {
                    const float* src = (const float*)A + (size_t)(row0 + r) * K + k0 + a_k8;
                    float4 v0 = *(const float4*)src;
                    float4 v1 = *(const float4*)(src + 4);
                    w.x = pack_h2(v0.x, v0.y);
                    w.y = pack_h2(v0.z, v0.w);
                    w.z = pack_h2(v1.x, v1.y);
                    w.w = pack_h2(v1.z, v1.w);
                } else {
                    w = *(const uint4*)((const __half*)A + (size_t)(row0 + r) * K + k0 + a_k8);
                }
            }
            int chunk = (tid & 3) ^ ((r >> 1) & 3);
            *(uint4*)(AsW + r * 16 + chunk * 4) = w;
        }
        // ---- B tile (32 x 128) -> fp16 smem [k][n] ----
#pragma unroll
        for (int p = 0; p < 4; ++p) {
            int kk = p * 8 + b_k;
            int kg = k0 + kk;
            int cg = col0 + b_n4;
            float4 v;
            if (cg < n1) v = *(const float4*)(B1 + (size_t)kg * n1 + cg);
            else         v = *(const float4*)(B2 + (size_t)kg * n2 + (cg - n1));
            uint2 w;
            w.x = pack_h2(v.x, v.y);
            w.y = pack_h2(v.z, v.w);
            *(uint2*)(BsW + kk * kBStrW + (b_n4 >> 1)) = w;
        }
        __syncthreads();

#pragma unroll
        for (int k16 = 0; k16 < 2; ++k16) {
            unsigned a[2][4];
            int c0 = (((k16 * 2)     ^ swz) << 2) + kkw;
            int c1 = (((k16 * 2 + 1) ^ swz) << 2) + kkw;
            a[0][0] = Arow[c0];        a[0][1] = Arow[128 + c0];
            a[0][2] = Arow[c1];        a[0][3] = Arow[128 + c1];
            a[1][0] = Arow[256 + c0];  a[1][1] = Arow[384 + c0];
            a[1][2] = Arow[256 + c1];  a[1][3] = Arow[384 + c1];

            uint32_t bAddr = bLaneBase + (uint32_t)(k16 * 16 * kBStrW * 4);
#pragma unroll
            for (int ni = 0; ni < 8; ++ni) {
                unsigned b0, b1;
                asm volatile(
                    "ldmatrix.sync.aligned.m8n8.x2.trans.shared.b16 {%0,%1}, [%2];"
                    : "=r"(b0), "=r"(b1) : "r"(bAddr + (uint32_t)(ni * 16)));
                mma_f16(d[0][ni], a[0], b0, b1);
                mma_f16(d[1][ni], a[1], b0, b1);
            }
        }
        __syncthreads();
    }

    const bool isOut1 = (col0 + wn < n1);
    const float* bias = isOut1 ? bias1 : bias2;
    const int Nc      = isOut1 ? n1 : n2;
    const int cbase   = isOut1 ? (col0 + wn) : (col0 + wn - n1);

#pragma unroll
    for (int mi = 0; mi < 2; ++mi) {
#pragma unroll
        for (int half = 0; half < 2; ++half) {
            int r = row0 + wm + mi * 16 + gr + half * 8;
            if (r >= M) continue;
#pragma unroll
            for (int ni = 0; ni < 8; ++ni) {
                int c = cbase + ni * 8 + 2 * kkw;
                float vx = d[mi][ni][half * 2 + 0] + __ldg(bias + c + 0);
                float vy = d[mi][ni][half * 2 + 1] + __ldg(bias + c + 1);
                if (isOut1) {
                    if (HALF1) {
                        __half* Co = (__half*)Cd1;
                        *(__half2*)(Co + (size_t)r * Nc + c) = __floats2half2_rn(vx, vy);
                    } else {
                        float* Co = (float*)Cd1;
                        *(float2*)(Co + (size_t)r * Nc + c) = make_float2(vx, vy);
                    }
                } else {
                    *(float2*)(Cd2 + (size_t)r * Nc + c) = make_float2(vx, vy);
                }
            }
        }
    }
}

// ---------------- helpers ----------------
__device__ __forceinline__ float leaky(float t) { return fmaxf(t, 0.2f * t); }

// ---------------- layer-1 fused edge phase (H=4, C=64, +bias +elu, fp16 out) ----
__global__ void gat_fused_l1(const int* __restrict__ off, const int* __restrict__ csr,
                             const __half* __restrict__ xl, const float* __restrict__ xr,
                             const float* __restrict__ att, const float* __restrict__ bias,
                             __half* __restrict__ out, int N) {
    int node = (blockIdx.x * blockDim.x + threadIdx.x) >> 5;
    if (node >= N) return;
    int lane = threadIdx.x & 31;

    const float4* prx = (const float4*)(xr + (size_t)node * 256);
    float4 xra = __ldg(prx + lane * 2);
    float4 xrb = __ldg(prx + lane * 2 + 1);
    const float4* pat = (const float4*)att;
    float4 ata = __ldg(pat + lane * 2);
    float4 atb = __ldg(pat + lane * 2 + 1);

    float acc[8];
#pragma unroll
    for (int i = 0; i < 8; ++i) acc[i] = 0.f;
    float m = -1e30f, s = 0.f;

    int e0 = __ldg(off + node), e1 = __ldg(off + node + 1);
#pragma unroll 2
    for (int e = e0; e < e1; ++e) {
        int src = __ldg(csr + e);
        uint4 u = __ldg((const uint4*)(xl + (size_t)src * 256) + lane);
        const __half2* hp = (const __half2*)&u;
        float2 f0 = __half22float2(hp[0]);
        float2 f1 = __half22float2(hp[1]);
        float2 f2 = __half22float2(hp[2]);
        float2 f3 = __half22float2(hp[3]);
        float v[8] = {f0.x, f0.y, f1.x, f1.y, f2.x, f2.y, f3.x, f3.y};

        float q = leaky(v[0] + xra.x) * ata.x;
        q = fmaf(leaky(v[1] + xra.y), ata.y, q);
        q = fmaf(leaky(v[2] + xra.z), ata.z, q);
        q = fmaf(leaky(v[3] + xra.w), ata.w, q);
        q = fmaf(leaky(v[4] + xrb.x), atb.x, q);
        q = fmaf(leaky(v[5] + xrb.y), atb.y, q);
        q = fmaf(leaky(v[6] + xrb.z), atb.z, q);
        q = fmaf(leaky(v[7] + xrb.w), atb.w, q);

        q += __shfl_xor_sync(0xffffffffu, q, 4);
        q += __shfl_xor_sync(0xffffffffu, q, 2);
        q += __shfl_xor_sync(0xffffffffu, q, 1);

        float nm = fmaxf(m, q);
        float sc = __expf(m - nm);
        float w  = __expf(q - nm);
        s = s * sc + w;
        m = nm;
#pragma unroll
        for (int i = 0; i < 8; ++i) acc[i] = fmaf(acc[i], sc, w * v[i]);
    }

    float inv = 1.f / s;
    const float4* pb = (const float4*)bias;
    float4 b0 = __ldg(pb + lane * 2), b1 = __ldg(pb + lane * 2 + 1);
    float o[8];
    o[0] = acc[0] * inv + b0.x;  o[1] = acc[1] * inv + b0.y;
    o[2] = acc[2] * inv + b0.z;  o[3] = acc[3] * inv + b0.w;
    o[4] = acc[4] * inv + b1.x;  o[5] = acc[5] * inv + b1.y;
    o[6] = acc[6] * inv + b1.z;  o[7] = acc[7] * inv + b1.w;
#pragma unroll
    for (int i = 0; i < 8; ++i) o[i] = (o[i] > 0.f) ? o[i] : expm1f(o[i]);

    uint4 w;
    __half2* wp = (__half2*)&w;
    wp[0] = __floats2half2_rn(o[0], o[1]);
    wp[1] = __floats2half2_rn(o[2], o[3]);
    wp[2] = __floats2half2_rn(o[4], o[5]);
    wp[3] = __floats2half2_rn(o[6], o[7]);
    *((uint4*)(out + (size_t)node * 256) + lane) = w;
}

// ---------------- layer-2 fused edge phase (H=1, C=64, +bias) ----------------
__global__ void gat_fused_l2(const int* __restrict__ off, const int* __restrict__ csr,
                             const __half* __restrict__ xl, const float* __restrict__ xr,
                             const float* __restrict__ att, const float* __restrict__ bias,
                             float* __restrict__ out, int N) {
    int node = (blockIdx.x * blockDim.x + threadIdx.x) >> 5;
    if (node >= N) return;
    int lane = threadIdx.x & 31;

    float2 xrv = __ldg((const float2*)(xr + (size_t)node * 64) + lane);
    float2 atv = __ldg((const float2*)att + lane);

    float2 acc = make_float2(0.f, 0.f);
    float m = -1e30f, s = 0.f;

    int e0 = __ldg(off + node), e1 = __ldg(off + node + 1);
#pragma unroll 2
    for (int e = e0; e < e1; ++e) {
        int src = __ldg(csr + e);
        __half2 hv = __ldg((const __half2*)(xl + (size_t)src * 64) + lane);
        float2 v = __half22float2(hv);
        float q = leaky(v.x + xrv.x) * atv.x;
        q = fmaf(leaky(v.y + xrv.y), atv.y, q);
#pragma unroll
        for (int o = 16; o; o >>= 1) q += __shfl_xor_sync(0xffffffffu, q, o);
        float nm = fmaxf(m, q);
        float sc = __expf(m - nm);
        float w  = __expf(q - nm);
        s = s * sc + w;
        m = nm;
        acc.x = fmaf(acc.x, sc, w * v.x);
        acc.y = fmaf(acc.y, sc, w * v.y);
    }

    float inv = 1.f / s;
    float2 bv = __ldg((const float2*)bias + lane);
    float2 o;
    o.x = acc.x * inv + bv.x;
    o.y = acc.y * inv + bv.y;
    *((float2*)(out + (size_t)node * 64) + lane) = o;
}

// ---------------- host launch ----------------
static __half* p_xl1 = nullptr;
static float*  p_xr1 = nullptr;
static __half* p_h   = nullptr;
static __half* p_xl2 = nullptr;
static float*  p_xr2 = nullptr;
static int*    p_deg = nullptr;
static int*    p_off = nullptr;
static int*    p_cur = nullptr;
static int*    p_bsum = nullptr;
static int*    p_csr = nullptr;
static cudaStream_t s_side = nullptr;
static cudaEvent_t  s_fork = nullptr, s_join = nullptr;

extern "C" void kernel_launch(void* const* d_in, const int* in_sizes, int n_in,
                              void* d_out, int out_size) {
    if (!p_xl1) {
        void* p;
        cudaGetSymbolAddress(&p, g_xl1);     p_xl1 = (__half*)p;
        cudaGetSymbolAddress(&p, g_xr1);     p_xr1 = (float*)p;
        cudaGetSymbolAddress(&p, g_h);       p_h   = (__half*)p;
        cudaGetSymbolAddress(&p, g_xl2);     p_xl2 = (__half*)p;
        cudaGetSymbolAddress(&p, g_xr2);     p_xr2 = (float*)p;
        cudaGetSymbolAddress(&p, g_deg);     p_deg = (int*)p;
        cudaGetSymbolAddress(&p, g_off);     p_off = (int*)p;
        cudaGetSymbolAddress(&p, g_cur);     p_cur = (int*)p;
        cudaGetSymbolAddress(&p, g_bsum);    p_bsum = (int*)p;
        cudaGetSymbolAddress(&p, g_csr_src); p_csr = (int*)p;
        cudaStreamCreateWithFlags(&s_side, cudaStreamNonBlocking);
        cudaEventCreateWithFlags(&s_fork, cudaEventDisableTiming);
        cudaEventCreateWithFlags(&s_join, cudaEventDisableTiming);
    }

    const float* x     = (const float*)d_in[0];
    const int*   ei    = (const int*)d_in[1];
    const float* Wl1   = (const float*)d_in[2];
    const float* bl1   = (const float*)d_in[3];
    const float* Wr1   = (const float*)d_in[4];
    const float* br1   = (const float*)d_in[5];
    const float* att1  = (const float*)d_in[6];
    const float* bias1 = (const float*)d_in[7];
    const float* Wl2   = (const float*)d_in[8];
    const float* bl2   = (const float*)d_in[9];
    const float* Wr2   = (const float*)d_in[10];
    const float* br2   = (const float*)d_in[11];
    const float* att2  = (const float*)d_in[12];
    const float* bias2 = (const float*)d_in[13];
    float* out = (float*)d_out;

    const int IN = 128;
    const int N  = in_sizes[0] / IN;
    const int E  = in_sizes[1] / 2;
    const int TE = E + N;

    const int T = 256;
    auto cdiv = [](int a, int b) { return (a + b - 1) / b; };
    int nb = cdiv(N, 1024);

    // ---- fork: CSR build on side stream ----
    cudaEventRecord(s_fork, 0);
    cudaStreamWaitEvent(s_side, s_fork, 0);

    count_deg<<<cdiv(TE, T), T, 0, s_side>>>(ei, E, TE, p_deg);               // launch 1
    scan_block<<<nb, 1024, 0, s_side>>>(p_deg, p_off, p_bsum, N);             // launch 2
    scan_add2<<<cdiv(N, T), T, 0, s_side>>>(p_off, p_bsum, p_cur, N, TE, nb); // launch 3

    // ---- layer 1 GEMM on main stream (launch 4: ncu window) ----
    {
        dim3 grid((kHC1 + kHC1) / 128, cdiv(N, 128));
        gemm_dual_tc<float, true><<<grid, 256>>>(x, Wl1, bl1, (void*)p_xl1, kHC1,
                                                 Wr1, br1, p_xr1, kHC1, N, IN);
    }

    scatter_csr<<<cdiv(TE, T), T, 0, s_side>>>(ei, E, TE, p_cur, p_csr);      // launch 5
    cudaEventRecord(s_join, s_side);

    // ---- join, then fused edge phase layer 1 -> h (fp16) ----
    cudaStreamWaitEvent(0, s_join, 0);
    gat_fused_l1<<<cdiv(N * 32, T), T>>>(p_off, p_csr, p_xl1, p_xr1, att1, bias1, p_h, N);

    // ---- layer 2 GEMM: A = h (fp16) ----
    {
        dim3 grid((kC2 + kC2) / 128, cdiv(N, 128));
        gemm_dual_tc<__half, true><<<grid, 256>>>(p_h, Wl2, bl2, (void*)p_xl2, kC2,
                                                  Wr2, br2, p_xr2, kC2, N, kHC1);
    }
    // ---- layer 2 fused edge phase -> out ----
    gat_fused_l2<<<cdiv(N * 32, T), T>>>(p_off, p_csr, p_xl2, p_xr2, att2, bias2, out, N);

    // ---- re-zero deg for the next replay ----
    zeroi<<<cdiv(N, T), T>>>(p_deg, N);
}

// round 14
// speedup vs baseline: 1.1658x; 1.1658x over previous
#include <cuda_runtime.h>
#include <cuda_fp16.h>
#include <cstddef>
#include <cstdint>

// ---------------- problem constants ----------------
constexpr int kMaxN  = 50016;
constexpr int kMaxE  = 400000;
constexpr int kMaxTE = kMaxN + kMaxE;
constexpr int kHC1   = 256;
constexpr int kC2    = 64;

// ---------------- device scratch ----------------
__device__ __half g_xl1[(size_t)kMaxN * kHC1];
__device__ float  g_xr1[(size_t)kMaxN * kHC1];
__device__ __half g_h  [(size_t)kMaxN * kHC1];
__device__ __half g_xl2[(size_t)kMaxN * kC2];
__device__ float  g_xr2[(size_t)kMaxN * kC2];
__device__ int    g_deg[kMaxN];                 // zero-init at load; re-zeroed at graph end
__device__ int    g_off[kMaxN + 1];
__device__ int    g_cur[kMaxN];
__device__ int    g_bsum[128];
__device__ int    g_csr_src[kMaxTE];

// ---------------- small utility kernels ----------------
__global__ void zeroi(int* p, int n) {
    int i = blockIdx.x * blockDim.x + threadIdx.x;
    if (i < n) p[i] = 0;
}

__global__ void count_deg(const int* __restrict__ ei, int E, int TE, int* __restrict__ deg) {
    int i = blockIdx.x * blockDim.x + threadIdx.x;
    if (i >= TE) return;
    int d = (i < E) ? ei[E + i] : (i - E);
    atomicAdd(&deg[d], 1);
}

__global__ void scan_block(const int* __restrict__ deg, int* __restrict__ off,
                           int* __restrict__ bsum, int n) {
    __shared__ int sh[1024];
    int tid = threadIdx.x;
    int i = blockIdx.x * 1024 + tid;
    int v = (i < n) ? deg[i] : 0;
    sh[tid] = v;
    __syncthreads();
    for (int o = 1; o < 1024; o <<= 1) {
        int t = (tid >= o) ? sh[tid - o] : 0;
        __syncthreads();
        sh[tid] += t;
        __syncthreads();
    }
    if (i < n) off[i] = sh[tid] - v;
    if (tid == 1023) bsum[blockIdx.x] = sh[1023];
}

__global__ void scan_add2(int* __restrict__ off, const int* __restrict__ bsum,
                          int* __restrict__ cur, int n, int total, int nb) {
    __shared__ int sh[128];
    int tid = threadIdx.x;
    if (tid < 128) sh[tid] = (tid < nb) ? bsum[tid] : 0;
    __syncthreads();
    for (int o = 1; o < 128; o <<= 1) {
        int u = (tid >= o && tid < 128) ? sh[tid - o] : 0;
        __syncthreads();
        if (tid < 128) sh[tid] += u;
        __syncthreads();
    }
    int i = blockIdx.x * blockDim.x + tid;
    if (i < n) {
        int b = i >> 10;
        int add = (b == 0) ? 0 : sh[b - 1];
        int v = off[i] + add;
        off[i] = v;
        cur[i] = v;
    }
    if (i == 0) off[n] = total;
}

__global__ void scatter_csr(const int* __restrict__ ei, int E, int TE,
                            int* __restrict__ cur, int* __restrict__ csr_src) {
    int i = blockIdx.x * blockDim.x + threadIdx.x;
    if (i >= TE) return;
    int s, d;
    if (i < E) { s = ei[i]; d = ei[E + i]; }
    else       { s = i - E; d = s; }
    int pos = atomicAdd(&cur[d], 1);
    csr_src[pos] = s;
}

// ---------------- FP16 tensor-core dual-output GEMM ----------------
// C = A[MxK] @ [B1|B2] + bias, fp32 accumulate, operands fp16 in smem.
// Block 128x128, k-chunk 32, 8 warps (4M x 2N), warp tile 32x64.
// mma.m16n8k16; B fragments via ldmatrix.x4.trans (2 n-tiles per LDSM).

__device__ __forceinline__ unsigned pack_h2(float a, float b) {
    __half2 h = __floats2half2_rn(a, b);
    return *(unsigned*)&h;
}

__device__ __forceinline__ void mma_f16(float* d, const unsigned* a, unsigned b0, unsigned b1) {
    asm volatile(
        "mma.sync.aligned.m16n8k16.row.col.f32.f16.f16.f32 "
        "{%0,%1,%2,%3}, {%4,%5,%6,%7}, {%8,%9}, {%0,%1,%2,%3};"
        : "+f"(d[0]), "+f"(d[1]), "+f"(d[2]), "+f"(d[3])
        : "r"(a[0]), "r"(a[1]), "r"(a[2]), "r"(a[3]), "r"(b0), "r"(b1));
}

constexpr int kBStrW = 68;   // Bs row stride in 32-bit words (64 + 4 pad)

// TA = float or __half for the A operand
template <typename TA, bool HALF1>
__global__ __launch_bounds__(256, 2)
void gemm_dual_tc(const TA* __restrict__ A,
                  const float* __restrict__ B1, const float* __restrict__ bias1,
                  void* __restrict__ Cd1, int n1,
                  const float* __restrict__ B2, const float* __restrict__ bias2,
                  float* __restrict__ Cd2, int n2,
                  int M, int K) {
    // As: [128 m][16 half2-words] with 4-word chunk XOR swizzle (chunk ^ ((r>>1)&3))
    // Bs: [32 k][64 half2-words + 4 pad] plain layout for ldmatrix
    __shared__ unsigned AsW[128 * 16];
    __shared__ unsigned BsW[32 * kBStrW];

    const int tid  = threadIdx.x;
    const int lane = tid & 31;
    const int wid  = tid >> 5;
    const int wm   = (wid & 3) * 32;
    const int wn   = (wid >> 2) * 64;
    const int row0 = blockIdx.y * 128;
    const int col0 = blockIdx.x * 128;
    const int gr   = lane >> 2;
    const int kkw  = lane & 3;
    const int swz  = (gr >> 1) & 3;

    float d[2][8][4];
#pragma unroll
    for (int mi = 0; mi < 2; ++mi)
#pragma unroll
        for (int ni = 0; ni < 8; ++ni)
#pragma unroll
            for (int r = 0; r < 4; ++r) d[mi][ni][r] = 0.f;

    const int a_row = tid >> 2;        // 0..63
    const int a_k8  = (tid & 3) * 8;   // half index within the 32-k chunk
    const int b_k   = tid >> 5;        // 0..7
    const int b_n4  = (tid & 31) * 4;

    const uint32_t bSm = (uint32_t)__cvta_generic_to_shared(BsW);
    // x4 ldmatrix: lanes 0-15 -> k rows (lane&15) at col group wn; lanes 16-31 ->
    // same k rows at col group wn+8 (offset +16 bytes).
    const uint32_t bLaneBase = bSm
        + (uint32_t)((((lane & 15) * kBStrW) + (wn >> 1) + ((lane >> 4) * 4)) * 4);

    const unsigned* Arow = AsW + (wm + gr) * 16;   // +128w = +8m, +256w = +16m, +384w = +24m

    for (int k0 = 0; k0 < K; k0 += 32) {
        // ---- A tile (128 x 32) -> fp16 smem ----
#pragma unroll
        for (int p = 0; p < 2; ++p) {
            int r = p * 64 + a_row;
            uint4 w = make_uint4(0u, 0u, 0u, 0u);
            if (row0 + r < M) {
                if constexpr (sizeof(TA) == 4) {
                    const float* src = (const float*)A + (size_t)(row0 + r) * K + k0 + a_k8;
                    float4 v0 = *(const float4*)src;
                    float4 v1 = *(const float4*)(src + 4);
                    w.x = pack_h2(v0.x, v0.y);
                    w.y = pack_h2(v0.z, v0.w);
                    w.z = pack_h2(v1.x, v1.y);
                    w.w = pack_h2(v1.z, v1.w);
                } else {
                    w = *(const uint4*)((const __half*)A + (size_t)(row0 + r) * K + k0 + a_k8);
                }
            }
            int chunk = (tid & 3) ^ ((r >> 1) & 3);
            *(uint4*)(AsW + r * 16 + chunk * 4) = w;
        }
        // ---- B tile (32 x 128) -> fp16 smem [k][n] ----
#pragma unroll
        for (int p = 0; p < 4; ++p) {
            int kk = p * 8 + b_k;
            int kg = k0 + kk;
            int cg = col0 + b_n4;
            float4 v;
            if (cg < n1) v = *(const float4*)(B1 + (size_t)kg * n1 + cg);
            else         v = *(const float4*)(B2 + (size_t)kg * n2 + (cg - n1));
            uint2 w;
            w.x = pack_h2(v.x, v.y);
            w.y = pack_h2(v.z, v.w);
            *(uint2*)(BsW + kk * kBStrW + (b_n4 >> 1)) = w;
        }
        __syncthreads();

#pragma unroll
        for (int k16 = 0; k16 < 2; ++k16) {
            unsigned a[2][4];
            int c0 = (((k16 * 2)     ^ swz) << 2) + kkw;
            int c1 = (((k16 * 2 + 1) ^ swz) << 2) + kkw;
            a[0][0] = Arow[c0];        a[0][1] = Arow[128 + c0];
            a[0][2] = Arow[c1];        a[0][3] = Arow[128 + c1];
            a[1][0] = Arow[256 + c0];  a[1][1] = Arow[384 + c0];
            a[1][2] = Arow[256 + c1];  a[1][3] = Arow[384 + c1];

            uint32_t bAddr = bLaneBase + (uint32_t)(k16 * 16 * kBStrW * 4);
#pragma unroll
            for (int ni2 = 0; ni2 < 4; ++ni2) {
                unsigned b0, b1, b2, b3;
                asm volatile(
                    "ldmatrix.sync.aligned.m8n8.x4.trans.shared.b16 {%0,%1,%2,%3}, [%4];"
                    : "=r"(b0), "=r"(b1), "=r"(b2), "=r"(b3)
                    : "r"(bAddr + (uint32_t)(ni2 * 32)));
                mma_f16(d[0][ni2 * 2 + 0], a[0], b0, b1);
                mma_f16(d[1][ni2 * 2 + 0], a[1], b0, b1);
                mma_f16(d[0][ni2 * 2 + 1], a[0], b2, b3);
                mma_f16(d[1][ni2 * 2 + 1], a[1], b2, b3);
            }
        }
        __syncthreads();
    }

    const bool isOut1 = (col0 + wn < n1);
    const float* bias = isOut1 ? bias1 : bias2;
    const int Nc      = isOut1 ? n1 : n2;
    const int cbase   = isOut1 ? (col0 + wn) : (col0 + wn - n1);

#pragma unroll
    for (int mi = 0; mi < 2; ++mi) {
#pragma unroll
        for (int half = 0; half < 2; ++half) {
            int r = row0 + wm + mi * 16 + gr + half * 8;
            if (r >= M) continue;
#pragma unroll
            for (int ni = 0; ni < 8; ++ni) {
                int c = cbase + ni * 8 + 2 * kkw;
                float vx = d[mi][ni][half * 2 + 0] + __ldg(bias + c + 0);
                float vy = d[mi][ni][half * 2 + 1] + __ldg(bias + c + 1);
                if (isOut1) {
                    if (HALF1) {
                        __half* Co = (__half*)Cd1;
                        *(__half2*)(Co + (size_t)r * Nc + c) = __floats2half2_rn(vx, vy);
                    } else {
                        float* Co = (float*)Cd1;
                        *(float2*)(Co + (size_t)r * Nc + c) = make_float2(vx, vy);
                    }
                } else {
                    *(float2*)(Cd2 + (size_t)r * Nc + c) = make_float2(vx, vy);
                }
            }
        }
    }
}

// ---------------- helpers ----------------
__device__ __forceinline__ float leaky(float t) { return fmaxf(t, 0.2f * t); }

// ---------------- layer-1 fused edge phase (H=4, C=64, +bias +elu, fp16 out) ----
__global__ void gat_fused_l1(const int* __restrict__ off, const int* __restrict__ csr,
                             const __half* __restrict__ xl, const float* __restrict__ xr,
                             const float* __restrict__ att, const float* __restrict__ bias,
                             __half* __restrict__ out, int N) {
    int node = (blockIdx.x * blockDim.x + threadIdx.x) >> 5;
    if (node >= N) return;
    int lane = threadIdx.x & 31;

    const float4* prx = (const float4*)(xr + (size_t)node * 256);
    float4 xra = __ldg(prx + lane * 2);
    float4 xrb = __ldg(prx + lane * 2 + 1);
    const float4* pat = (const float4*)att;
    float4 ata = __ldg(pat + lane * 2);
    float4 atb = __ldg(pat + lane * 2 + 1);

    float acc[8];
#pragma unroll
    for (int i = 0; i < 8; ++i) acc[i] = 0.f;
    float m = -1e30f, s = 0.f;

    int e0 = __ldg(off + node), e1 = __ldg(off + node + 1);
#pragma unroll 2
    for (int e = e0; e < e1; ++e) {
        int src = __ldg(csr + e);
        uint4 u = __ldg((const uint4*)(xl + (size_t)src * 256) + lane);
        const __half2* hp = (const __half2*)&u;
        float2 f0 = __half22float2(hp[0]);
        float2 f1 = __half22float2(hp[1]);
        float2 f2 = __half22float2(hp[2]);
        float2 f3 = __half22float2(hp[3]);
        float v[8] = {f0.x, f0.y, f1.x, f1.y, f2.x, f2.y, f3.x, f3.y};

        float q = leaky(v[0] + xra.x) * ata.x;
        q = fmaf(leaky(v[1] + xra.y), ata.y, q);
        q = fmaf(leaky(v[2] + xra.z), ata.z, q);
        q = fmaf(leaky(v[3] + xra.w), ata.w, q);
        q = fmaf(leaky(v[4] + xrb.x), atb.x, q);
        q = fmaf(leaky(v[5] + xrb.y), atb.y, q);
        q = fmaf(leaky(v[6] + xrb.z), atb.z, q);
        q = fmaf(leaky(v[7] + xrb.w), atb.w, q);

        q += __shfl_xor_sync(0xffffffffu, q, 4);
        q += __shfl_xor_sync(0xffffffffu, q, 2);
        q += __shfl_xor_sync(0xffffffffu, q, 1);

        float nm = fmaxf(m, q);
        float sc = __expf(m - nm);
        float w  = __expf(q - nm);
        s = s * sc + w;
        m = nm;
#pragma unroll
        for (int i = 0; i < 8; ++i) acc[i] = fmaf(acc[i], sc, w * v[i]);
    }

    float inv = 1.f / s;
    const float4* pb = (const float4*)bias;
    float4 b0 = __ldg(pb + lane * 2), b1 = __ldg(pb + lane * 2 + 1);
    float o[8];
    o[0] = acc[0] * inv + b0.x;  o[1] = acc[1] * inv + b0.y;
    o[2] = acc[2] * inv + b0.z;  o[3] = acc[3] * inv + b0.w;
    o[4] = acc[4] * inv + b1.x;  o[5] = acc[5] * inv + b1.y;
    o[6] = acc[6] * inv + b1.z;  o[7] = acc[7] * inv + b1.w;
#pragma unroll
    for (int i = 0; i < 8; ++i) o[i] = (o[i] > 0.f) ? o[i] : expm1f(o[i]);

    uint4 w;
    __half2* wp = (__half2*)&w;
    wp[0] = __floats2half2_rn(o[0], o[1]);
    wp[1] = __floats2half2_rn(o[2], o[3]);
    wp[2] = __floats2half2_rn(o[4], o[5]);
    wp[3] = __floats2half2_rn(o[6], o[7]);
    *((uint4*)(out + (size_t)node * 256) + lane) = w;
}

// ---------------- layer-2 fused edge phase (H=1, C=64, +bias) ----------------
__global__ void gat_fused_l2(const int* __restrict__ off, const int* __restrict__ csr,
                             const __half* __restrict__ xl, const float* __restrict__ xr,
                             const float* __restrict__ att, const float* __restrict__ bias,
                             float* __restrict__ out, int N) {
    int node = (blockIdx.x * blockDim.x + threadIdx.x) >> 5;
    if (node >= N) return;
    int lane = threadIdx.x & 31;

    float2 xrv = __ldg((const float2*)(xr + (size_t)node * 64) + lane);
    float2 atv = __ldg((const float2*)att + lane);

    float2 acc = make_float2(0.f, 0.f);
    float m = -1e30f, s = 0.f;

    int e0 = __ldg(off + node), e1 = __ldg(off + node + 1);
#pragma unroll 2
    for (int e = e0; e < e1; ++e) {
        int src = __ldg(csr + e);
        __half2 hv = __ldg((const __half2*)(xl + (size_t)src * 64) + lane);
        float2 v = __half22float2(hv);
        float q = leaky(v.x + xrv.x) * atv.x;
        q = fmaf(leaky(v.y + xrv.y), atv.y, q);
#pragma unroll
        for (int o = 16; o; o >>= 1) q += __shfl_xor_sync(0xffffffffu, q, o);
        float nm = fmaxf(m, q);
        float sc = __expf(m - nm);
        float w  = __expf(q - nm);
        s = s * sc + w;
        m = nm;
        acc.x = fmaf(acc.x, sc, w * v.x);
        acc.y = fmaf(acc.y, sc, w * v.y);
    }

    float inv = 1.f / s;
    float2 bv = __ldg((const float2*)bias + lane);
    float2 o;
    o.x = acc.x * inv + bv.x;
    o.y = acc.y * inv + bv.y;
    *((float2*)(out + (size_t)node * 64) + lane) = o;
}

// ---------------- host launch ----------------
static __half* p_xl1 = nullptr;
static float*  p_xr1 = nullptr;
static __half* p_h   = nullptr;
static __half* p_xl2 = nullptr;
static float*  p_xr2 = nullptr;
static int*    p_deg = nullptr;
static int*    p_off = nullptr;
static int*    p_cur = nullptr;
static int*    p_bsum = nullptr;
static int*    p_csr = nullptr;
static cudaStream_t s_side = nullptr;
static cudaEvent_t  s_fork = nullptr, s_join = nullptr;

extern "C" void kernel_launch(void* const* d_in, const int* in_sizes, int n_in,
                              void* d_out, int out_size) {
    if (!p_xl1) {
        void* p;
        cudaGetSymbolAddress(&p, g_xl1);     p_xl1 = (__half*)p;
        cudaGetSymbolAddress(&p, g_xr1);     p_xr1 = (float*)p;
        cudaGetSymbolAddress(&p, g_h);       p_h   = (__half*)p;
        cudaGetSymbolAddress(&p, g_xl2);     p_xl2 = (__half*)p;
        cudaGetSymbolAddress(&p, g_xr2);     p_xr2 = (float*)p;
        cudaGetSymbolAddress(&p, g_deg);     p_deg = (int*)p;
        cudaGetSymbolAddress(&p, g_off);     p_off = (int*)p;
        cudaGetSymbolAddress(&p, g_cur);     p_cur = (int*)p;
        cudaGetSymbolAddress(&p, g_bsum);    p_bsum = (int*)p;
        cudaGetSymbolAddress(&p, g_csr_src); p_csr = (int*)p;
        cudaStreamCreateWithFlags(&s_side, cudaStreamNonBlocking);
        cudaEventCreateWithFlags(&s_fork, cudaEventDisableTiming);
        cudaEventCreateWithFlags(&s_join, cudaEventDisableTiming);
    }

    const float* x     = (const float*)d_in[0];
    const int*   ei    = (const int*)d_in[1];
    const float* Wl1   = (const float*)d_in[2];
    const float* bl1   = (const float*)d_in[3];
    const float* Wr1   = (const float*)d_in[4];
    const float* br1   = (const float*)d_in[5];
    const float* att1  = (const float*)d_in[6];
    const float* bias1 = (const float*)d_in[7];
    const float* Wl2   = (const float*)d_in[8];
    const float* bl2   = (const float*)d_in[9];
    const float* Wr2   = (const float*)d_in[10];
    const float* br2   = (const float*)d_in[11];
    const float* att2  = (const float*)d_in[12];
    const float* bias2 = (const float*)d_in[13];
    float* out = (float*)d_out;

    const int IN = 128;
    const int N  = in_sizes[0] / IN;
    const int E  = in_sizes[1] / 2;
    const int TE = E + N;

    const int T = 256;
    auto cdiv = [](int a, int b) { return (a + b - 1) / b; };
    int nb = cdiv(N, 1024);

    // ---- fork: CSR build on side stream ----
    cudaEventRecord(s_fork, 0);
    cudaStreamWaitEvent(s_side, s_fork, 0);

    count_deg<<<cdiv(TE, T), T, 0, s_side>>>(ei, E, TE, p_deg);               // launch 1
    scan_block<<<nb, 1024, 0, s_side>>>(p_deg, p_off, p_bsum, N);             // launch 2
    scan_add2<<<cdiv(N, T), T, 0, s_side>>>(p_off, p_bsum, p_cur, N, TE, nb); // launch 3

    // ---- layer 1 GEMM on main stream (launch 4: ncu window) ----
    {
        dim3 grid((kHC1 + kHC1) / 128, cdiv(N, 128));
        gemm_dual_tc<float, true><<<grid, 256>>>(x, Wl1, bl1, (void*)p_xl1, kHC1,
                                                 Wr1, br1, p_xr1, kHC1, N, IN);
    }

    scatter_csr<<<cdiv(TE, T), T, 0, s_side>>>(ei, E, TE, p_cur, p_csr);      // launch 5
    cudaEventRecord(s_join, s_side);

    // ---- join, then fused edge phase layer 1 -> h (fp16) ----
    cudaStreamWaitEvent(0, s_join, 0);
    gat_fused_l1<<<cdiv(N * 32, T), T>>>(p_off, p_csr, p_xl1, p_xr1, att1, bias1, p_h, N);

    // ---- layer 2 GEMM: A = h (fp16) ----
    {
        dim3 grid((kC2 + kC2) / 128, cdiv(N, 128));
        gemm_dual_tc<__half, true><<<grid, 256>>>(p_h, Wl2, bl2, (void*)p_xl2, kC2,
                                                  Wr2, br2, p_xr2, kC2, N, kHC1);
    }
    // ---- layer 2 fused edge phase -> out ----
    gat_fused_l2<<<cdiv(N * 32, T), T>>>(p_off, p_csr, p_xl2, p_xr2, att2, bias2, out, N);

    // ---- re-zero deg for the next replay ----
    zeroi<<<cdiv(N, T), T>>>(p_deg, N);
}

// round 15
// speedup vs baseline: 1.1715x; 1.0049x over previous
#include <cuda_runtime.h>
#include <cuda_fp16.h>
#include <cstddef>
#include <cstdint>

// ---------------- problem constants ----------------
constexpr int kMaxN  = 50016;
constexpr int kMaxE  = 400000;
constexpr int kMaxTE = kMaxN + kMaxE;
constexpr int kHC1   = 256;
constexpr int kC2    = 64;

// ---------------- device scratch ----------------
__device__ __half g_xl1[(size_t)kMaxN * kHC1];
__device__ float  g_xr1[(size_t)kMaxN * kHC1];
__device__ __half g_h  [(size_t)kMaxN * kHC1];
__device__ __half g_xl2[(size_t)kMaxN * kC2];
__device__ float  g_xr2[(size_t)kMaxN * kC2];
__device__ int    g_deg[kMaxN];                 // zero-init at load; re-zeroed at graph end
__device__ int    g_off[kMaxN + 1];
__device__ int    g_cur[kMaxN];
__device__ int    g_bsum[128];
__device__ int    g_csr_src[kMaxTE];

// ---------------- small utility kernels ----------------
__global__ void zeroi(int* p, int n) {
    int i = blockIdx.x * blockDim.x + threadIdx.x;
    if (i < n) p[i] = 0;
}

__global__ void count_deg(const int* __restrict__ ei, int E, int TE, int* __restrict__ deg) {
    int i = blockIdx.x * blockDim.x + threadIdx.x;
    if (i >= TE) return;
    int d = (i < E) ? ei[E + i] : (i - E);
    atomicAdd(&deg[d], 1);
}

__global__ void scan_block(const int* __restrict__ deg, int* __restrict__ off,
                           int* __restrict__ bsum, int n) {
    __shared__ int sh[1024];
    int tid = threadIdx.x;
    int i = blockIdx.x * 1024 + tid;
    int v = (i < n) ? deg[i] : 0;
    sh[tid] = v;
    __syncthreads();
    for (int o = 1; o < 1024; o <<= 1) {
        int t = (tid >= o) ? sh[tid - o] : 0;
        __syncthreads();
        sh[tid] += t;
        __syncthreads();
    }
    if (i < n) off[i] = sh[tid] - v;
    if (tid == 1023) bsum[blockIdx.x] = sh[1023];
}

__global__ void scan_add2(int* __restrict__ off, const int* __restrict__ bsum,
                          int* __restrict__ cur, int n, int total, int nb) {
    __shared__ int sh[128];
    int tid = threadIdx.x;
    if (tid < 128) sh[tid] = (tid < nb) ? bsum[tid] : 0;
    __syncthreads();
    for (int o = 1; o < 128; o <<= 1) {
        int u = (tid >= o && tid < 128) ? sh[tid - o] : 0;
        __syncthreads();
        if (tid < 128) sh[tid] += u;
        __syncthreads();
    }
    int i = blockIdx.x * blockDim.x + tid;
    if (i < n) {
        int b = i >> 10;
        int add = (b == 0) ? 0 : sh[b - 1];
        int v = off[i] + add;
        off[i] = v;
        cur[i] = v;
    }
    if (i == 0) off[n] = total;
}

__global__ void scatter_csr(const int* __restrict__ ei, int E, int TE,
                            int* __restrict__ cur, int* __restrict__ csr_src) {
    int i = blockIdx.x * blockDim.x + threadIdx.x;
    if (i >= TE) return;
    int s, d;
    if (i < E) { s = ei[i]; d = ei[E + i]; }
    else       { s = i - E; d = s; }
    int pos = atomicAdd(&cur[d], 1);
    csr_src[pos] = s;
}

// ---------------- FP16 tensor-core dual-output GEMM ----------------
// C = A[MxK] @ [B1|B2] + bias, fp32 accumulate, operands fp16 in smem.
// Block 128x128, k-chunk 32, 8 warps (4M x 2N), warp tile 32x64.
// mma.m16n8k16; A fragments via ldmatrix.x4, B via ldmatrix.x4.trans.

__device__ __forceinline__ unsigned pack_h2(float a, float b) {
    __half2 h = __floats2half2_rn(a, b);
    return *(unsigned*)&h;
}

__device__ __forceinline__ void mma_f16(float* d, const unsigned* a, unsigned b0, unsigned b1) {
    asm volatile(
        "mma.sync.aligned.m16n8k16.row.col.f32.f16.f16.f32 "
        "{%0,%1,%2,%3}, {%4,%5,%6,%7}, {%8,%9}, {%0,%1,%2,%3};"
        : "+f"(d[0]), "+f"(d[1]), "+f"(d[2]), "+f"(d[3])
        : "r"(a[0]), "r"(a[1]), "r"(a[2]), "r"(a[3]), "r"(b0), "r"(b1));
}

constexpr int kBStrW = 68;   // Bs row stride in 32-bit words (64 + 4 pad)

// TA = float or __half for the A operand
template <typename TA, bool HALF1>
__global__ __launch_bounds__(256, 2)
void gemm_dual_tc(const TA* __restrict__ A,
                  const float* __restrict__ B1, const float* __restrict__ bias1,
                  void* __restrict__ Cd1, int n1,
                  const float* __restrict__ B2, const float* __restrict__ bias2,
                  float* __restrict__ Cd2, int n2,
                  int M, int K) {
    // As: [128 m][16 half2-words] with 4-word chunk XOR swizzle (chunk ^ ((r>>1)&3))
    // Bs: [32 k][64 half2-words + 4 pad] plain layout for ldmatrix
    __shared__ unsigned AsW[128 * 16];
    __shared__ unsigned BsW[32 * kBStrW];

    const int tid  = threadIdx.x;
    const int lane = tid & 31;
    const int wid  = tid >> 5;
    const int wm   = (wid & 3) * 32;
    const int wn   = (wid >> 2) * 64;
    const int row0 = blockIdx.y * 128;
    const int col0 = blockIdx.x * 128;
    const int gr   = lane >> 2;
    const int kkw  = lane & 3;

    float d[2][8][4];
#pragma unroll
    for (int mi = 0; mi < 2; ++mi)
#pragma unroll
        for (int ni = 0; ni < 8; ++ni)
#pragma unroll
            for (int r = 0; r < 4; ++r) d[mi][ni][r] = 0.f;

    const int a_row = tid >> 2;        // 0..63
    const int a_k8  = (tid & 3) * 8;   // half index within the 32-k chunk
    const int b_k   = tid >> 5;        // 0..7
    const int b_n4  = (tid & 31) * 4;

    const uint32_t bSm = (uint32_t)__cvta_generic_to_shared(BsW);
    // B x4 ldmatrix: lanes 0-15 -> k rows (lane&15) at col group wn; lanes 16-31 ->
    // same k rows at col group wn+8 (offset +16 bytes).
    const uint32_t bLaneBase = bSm
        + (uint32_t)((((lane & 15) * kBStrW) + (wn >> 1) + ((lane >> 4) * 4)) * 4);

    // A x4 ldmatrix (non-trans): matrix j addressed by lanes [8j..8j+8):
    //   j=0: rows wm..+7   k 0-7 | j=1: rows wm+8..+15 k 0-7
    //   j=2: rows wm..+7   k 8-15| j=3: rows wm+8..+15 k 8-15  (of the k16 tile)
    const uint32_t aSm = (uint32_t)__cvta_generic_to_shared(AsW);
    const int lj  = lane >> 3;          // matrix index 0..3
    const int lhi = lane >> 4;          // chunk high bit (k8 group)
    const int ar0 = wm + ((lj & 1) << 3) + (lane & 7);   // row for mi=0
    const int ar1 = ar0 + 16;                            // row for mi=1
    const uint32_t aBase0 = aSm + (uint32_t)(ar0 * 64);
    const uint32_t aBase1 = aSm + (uint32_t)(ar1 * 64);
    const int aswz0 = (ar0 >> 1) & 3;
    const int aswz1 = (ar1 >> 1) & 3;

    for (int k0 = 0; k0 < K; k0 += 32) {
        // ---- A tile (128 x 32) -> fp16 smem ----
#pragma unroll
        for (int p = 0; p < 2; ++p) {
            int r = p * 64 + a_row;
            uint4 w = make_uint4(0u, 0u, 0u, 0u);
            if (row0 + r < M) {
                if constexpr (sizeof(TA) == 4) {
                    const float* src = (const float*)A + (size_t)(row0 + r) * K + k0 + a_k8;
                    float4 v0 = *(const float4*)src;
                    float4 v1 = *(const float4*)(src + 4);
                    w.x = pack_h2(v0.x, v0.y);
                    w.y = pack_h2(v0.z, v0.w);
                    w.z = pack_h2(v1.x, v1.y);
                    w.w = pack_h2(v1.z, v1.w);
                } else {
                    w = *(const uint4*)((const __half*)A + (size_t)(row0 + r) * K + k0 + a_k8);
                }
            }
            int chunk = (tid & 3) ^ ((r >> 1) & 3);
            *(uint4*)(AsW + r * 16 + chunk * 4) = w;
        }
        // ---- B tile (32 x 128) -> fp16 smem [k][n] ----
#pragma unroll
        for (int p = 0; p < 4; ++p) {
            int kk = p * 8 + b_k;
            int kg = k0 + kk;
            int cg = col0 + b_n4;
            float4 v;
            if (cg < n1) v = *(const float4*)(B1 + (size_t)kg * n1 + cg);
            else         v = *(const float4*)(B2 + (size_t)kg * n2 + (cg - n1));
            uint2 w;
            w.x = pack_h2(v.x, v.y);
            w.y = pack_h2(v.z, v.w);
            *(uint2*)(BsW + kk * kBStrW + (b_n4 >> 1)) = w;
        }
        __syncthreads();

#pragma unroll
        for (int k16 = 0; k16 < 2; ++k16) {
            unsigned a[2][4];
            int ch = k16 * 2 + lhi;
            uint32_t ad0 = aBase0 + (uint32_t)(((ch ^ aswz0) << 4));
            uint32_t ad1 = aBase1 + (uint32_t)(((ch ^ aswz1) << 4));
            asm volatile(
                "ldmatrix.sync.aligned.m8n8.x4.shared.b16 {%0,%1,%2,%3}, [%4];"
                : "=r"(a[0][0]), "=r"(a[0][1]), "=r"(a[0][2]), "=r"(a[0][3])
                : "r"(ad0));
            asm volatile(
                "ldmatrix.sync.aligned.m8n8.x4.shared.b16 {%0,%1,%2,%3}, [%4];"
                : "=r"(a[1][0]), "=r"(a[1][1]), "=r"(a[1][2]), "=r"(a[1][3])
                : "r"(ad1));

            uint32_t bAddr = bLaneBase + (uint32_t)(k16 * 16 * kBStrW * 4);
#pragma unroll
            for (int ni2 = 0; ni2 < 4; ++ni2) {
                unsigned b0, b1, b2, b3;
                asm volatile(
                    "ldmatrix.sync.aligned.m8n8.x4.trans.shared.b16 {%0,%1,%2,%3}, [%4];"
                    : "=r"(b0), "=r"(b1), "=r"(b2), "=r"(b3)
                    : "r"(bAddr + (uint32_t)(ni2 * 32)));
                mma_f16(d[0][ni2 * 2 + 0], a[0], b0, b1);
                mma_f16(d[1][ni2 * 2 + 0], a[1], b0, b1);
                mma_f16(d[0][ni2 * 2 + 1], a[0], b2, b3);
                mma_f16(d[1][ni2 * 2 + 1], a[1], b2, b3);
            }
        }
        __syncthreads();
    }

    const bool isOut1 = (col0 + wn < n1);
    const float* bias = isOut1 ? bias1 : bias2;
    const int Nc      = isOut1 ? n1 : n2;
    const int cbase   = isOut1 ? (col0 + wn) : (col0 + wn - n1);

#pragma unroll
    for (int mi = 0; mi < 2; ++mi) {
#pragma unroll
        for (int half = 0; half < 2; ++half) {
            int r = row0 + wm + mi * 16 + gr + half * 8;
            if (r >= M) continue;
#pragma unroll
            for (int ni = 0; ni < 8; ++ni) {
                int c = cbase + ni * 8 + 2 * kkw;
                float vx = d[mi][ni][half * 2 + 0] + __ldg(bias + c + 0);
                float vy = d[mi][ni][half * 2 + 1] + __ldg(bias + c + 1);
                if (isOut1) {
                    if (HALF1) {
                        __half* Co = (__half*)Cd1;
                        *(__half2*)(Co + (size_t)r * Nc + c) = __floats2half2_rn(vx, vy);
                    } else {
                        float* Co = (float*)Cd1;
                        *(float2*)(Co + (size_t)r * Nc + c) = make_float2(vx, vy);
                    }
                } else {
                    *(float2*)(Cd2 + (size_t)r * Nc + c) = make_float2(vx, vy);
                }
            }
        }
    }
}

// ---------------- helpers ----------------
__device__ __forceinline__ float leaky(float t) { return fmaxf(t, 0.2f * t); }

// ---------------- layer-1 fused edge phase (H=4, C=64, +bias +elu, fp16 out) ----
__global__ void gat_fused_l1(const int* __restrict__ off, const int* __restrict__ csr,
                             const __half* __restrict__ xl, const float* __restrict__ xr,
                             const float* __restrict__ att, const float* __restrict__ bias,
                             __half* __restrict__ out, int N) {
    int node = (blockIdx.x * blockDim.x + threadIdx.x) >> 5;
    if (node >= N) return;
    int lane = threadIdx.x & 31;

    const float4* prx = (const float4*)(xr + (size_t)node * 256);
    float4 xra = __ldg(prx + lane * 2);
    float4 xrb = __ldg(prx + lane * 2 + 1);
    const float4* pat = (const float4*)att;
    float4 ata = __ldg(pat + lane * 2);
    float4 atb = __ldg(pat + lane * 2 + 1);

    float acc[8];
#pragma unroll
    for (int i = 0; i < 8; ++i) acc[i] = 0.f;
    float m = -1e30f, s = 0.f;

    int e0 = __ldg(off + node), e1 = __ldg(off + node + 1);
#pragma unroll 2
    for (int e = e0; e < e1; ++e) {
        int src = __ldg(csr + e);
        uint4 u = __ldg((const uint4*)(xl + (size_t)src * 256) + lane);
        const __half2* hp = (const __half2*)&u;
        float2 f0 = __half22float2(hp[0]);
        float2 f1 = __half22float2(hp[1]);
        float2 f2 = __half22float2(hp[2]);
        float2 f3 = __half22float2(hp[3]);
        float v[8] = {f0.x, f0.y, f1.x, f1.y, f2.x, f2.y, f3.x, f3.y};

        float q = leaky(v[0] + xra.x) * ata.x;
        q = fmaf(leaky(v[1] + xra.y), ata.y, q);
        q = fmaf(leaky(v[2] + xra.z), ata.z, q);
        q = fmaf(leaky(v[3] + xra.w), ata.w, q);
        q = fmaf(leaky(v[4] + xrb.x), atb.x, q);
        q = fmaf(leaky(v[5] + xrb.y), atb.y, q);
        q = fmaf(leaky(v[6] + xrb.z), atb.z, q);
        q = fmaf(leaky(v[7] + xrb.w), atb.w, q);

        q += __shfl_xor_sync(0xffffffffu, q, 4);
        q += __shfl_xor_sync(0xffffffffu, q, 2);
        q += __shfl_xor_sync(0xffffffffu, q, 1);

        float nm = fmaxf(m, q);
        float sc = __expf(m - nm);
        float w  = __expf(q - nm);
        s = s * sc + w;
        m = nm;
#pragma unroll
        for (int i = 0; i < 8; ++i) acc[i] = fmaf(acc[i], sc, w * v[i]);
    }

    float inv = 1.f / s;
    const float4* pb = (const float4*)bias;
    float4 b0 = __ldg(pb + lane * 2), b1 = __ldg(pb + lane * 2 + 1);
    float o[8];
    o[0] = acc[0] * inv + b0.x;  o[1] = acc[1] * inv + b0.y;
    o[2] = acc[2] * inv + b0.z;  o[3] = acc[3] * inv + b0.w;
    o[4] = acc[4] * inv + b1.x;  o[5] = acc[5] * inv + b1.y;
    o[6] = acc[6] * inv + b1.z;  o[7] = acc[7] * inv + b1.w;
#pragma unroll
    for (int i = 0; i < 8; ++i) o[i] = (o[i] > 0.f) ? o[i] : expm1f(o[i]);

    uint4 w;
    __half2* wp = (__half2*)&w;
    wp[0] = __floats2half2_rn(o[0], o[1]);
    wp[1] = __floats2half2_rn(o[2], o[3]);
    wp[2] = __floats2half2_rn(o[4], o[5]);
    wp[3] = __floats2half2_rn(o[6], o[7]);
    *((uint4*)(out + (size_t)node * 256) + lane) = w;
}

// ---------------- layer-2 fused edge phase (H=1, C=64, +bias) ----------------
__global__ void gat_fused_l2(const int* __restrict__ off, const int* __restrict__ csr,
                             const __half* __restrict__ xl, const float* __restrict__ xr,
                             const float* __restrict__ att, const float* __restrict__ bias,
                             float* __restrict__ out, int N) {
    int node = (blockIdx.x * blockDim.x + threadIdx.x) >> 5;
    if (node >= N) return;
    int lane = threadIdx.x & 31;

    float2 xrv = __ldg((const float2*)(xr + (size_t)node * 64) + lane);
    float2 atv = __ldg((const float2*)att + lane);

    float2 acc = make_float2(0.f, 0.f);
    float m = -1e30f, s = 0.f;

    int e0 = __ldg(off + node), e1 = __ldg(off + node + 1);
#pragma unroll 2
    for (int e = e0; e < e1; ++e) {
        int src = __ldg(csr + e);
        __half2 hv = __ldg((const __half2*)(xl + (size_t)src * 64) + lane);
        float2 v = __half22float2(hv);
        float q = leaky(v.x + xrv.x) * atv.x;
        q = fmaf(leaky(v.y + xrv.y), atv.y, q);
#pragma unroll
        for (int o = 16; o; o >>= 1) q += __shfl_xor_sync(0xffffffffu, q, o);
        float nm = fmaxf(m, q);
        float sc = __expf(m - nm);
        float w  = __expf(q - nm);
        s = s * sc + w;
        m = nm;
        acc.x = fmaf(acc.x, sc, w * v.x);
        acc.y = fmaf(acc.y, sc, w * v.y);
    }

    float inv = 1.f / s;
    float2 bv = __ldg((const float2*)bias + lane);
    float2 o;
    o.x = acc.x * inv + bv.x;
    o.y = acc.y * inv + bv.y;
    *((float2*)(out + (size_t)node * 64) + lane) = o;
}

// ---------------- host launch ----------------
static __half* p_xl1 = nullptr;
static float*  p_xr1 = nullptr;
static __half* p_h   = nullptr;
static __half* p_xl2 = nullptr;
static float*  p_xr2 = nullptr;
static int*    p_deg = nullptr;
static int*    p_off = nullptr;
static int*    p_cur = nullptr;
static int*    p_bsum = nullptr;
static int*    p_csr = nullptr;
static cudaStream_t s_side = nullptr;
static cudaEvent_t  s_fork = nullptr, s_join = nullptr;

extern "C" void kernel_launch(void* const* d_in, const int* in_sizes, int n_in,
                              void* d_out, int out_size) {
    if (!p_xl1) {
        void* p;
        cudaGetSymbolAddress(&p, g_xl1);     p_xl1 = (__half*)p;
        cudaGetSymbolAddress(&p, g_xr1);     p_xr1 = (float*)p;
        cudaGetSymbolAddress(&p, g_h);       p_h   = (__half*)p;
        cudaGetSymbolAddress(&p, g_xl2);     p_xl2 = (__half*)p;
        cudaGetSymbolAddress(&p, g_xr2);     p_xr2 = (float*)p;
        cudaGetSymbolAddress(&p, g_deg);     p_deg = (int*)p;
        cudaGetSymbolAddress(&p, g_off);     p_off = (int*)p;
        cudaGetSymbolAddress(&p, g_cur);     p_cur = (int*)p;
        cudaGetSymbolAddress(&p, g_bsum);    p_bsum = (int*)p;
        cudaGetSymbolAddress(&p, g_csr_src); p_csr = (int*)p;
        cudaStreamCreateWithFlags(&s_side, cudaStreamNonBlocking);
        cudaEventCreateWithFlags(&s_fork, cudaEventDisableTiming);
        cudaEventCreateWithFlags(&s_join, cudaEventDisableTiming);
    }

    const float* x     = (const float*)d_in[0];
    const int*   ei    = (const int*)d_in[1];
    const float* Wl1   = (const float*)d_in[2];
    const float* bl1   = (const float*)d_in[3];
    const float* Wr1   = (const float*)d_in[4];
    const float* br1   = (const float*)d_in[5];
    const float* att1  = (const float*)d_in[6];
    const float* bias1 = (const float*)d_in[7];
    const float* Wl2   = (const float*)d_in[8];
    const float* bl2   = (const float*)d_in[9];
    const float* Wr2   = (const float*)d_in[10];
    const float* br2   = (const float*)d_in[11];
    const float* att2  = (const float*)d_in[12];
    const float* bias2 = (const float*)d_in[13];
    float* out = (float*)d_out;

    const int IN = 128;
    const int N  = in_sizes[0] / IN;
    const int E  = in_sizes[1] / 2;
    const int TE = E + N;

    const int T = 256;
    auto cdiv = [](int a, int b) { return (a + b - 1) / b; };
    int nb = cdiv(N, 1024);

    // ---- fork: CSR build on side stream ----
    cudaEventRecord(s_fork, 0);
    cudaStreamWaitEvent(s_side, s_fork, 0);

    count_deg<<<cdiv(TE, T), T, 0, s_side>>>(ei, E, TE, p_deg);               // launch 1
    scan_block<<<nb, 1024, 0, s_side>>>(p_deg, p_off, p_bsum, N);             // launch 2
    scan_add2<<<cdiv(N, T), T, 0, s_side>>>(p_off, p_bsum, p_cur, N, TE, nb); // launch 3

    // ---- layer 1 GEMM on main stream (launch 4: ncu window) ----
    {
        dim3 grid((kHC1 + kHC1) / 128, cdiv(N, 128));
        gemm_dual_tc<float, true><<<grid, 256>>>(x, Wl1, bl1, (void*)p_xl1, kHC1,
                                                 Wr1, br1, p_xr1, kHC1, N, IN);
    }

    scatter_csr<<<cdiv(TE, T), T, 0, s_side>>>(ei, E, TE, p_cur, p_csr);      // launch 5
    cudaEventRecord(s_join, s_side);

    // ---- join, then fused edge phase layer 1 -> h (fp16) ----
    cudaStreamWaitEvent(0, s_join, 0);
    gat_fused_l1<<<cdiv(N * 32, T), T>>>(p_off, p_csr, p_xl1, p_xr1, att1, bias1, p_h, N);

    // ---- layer 2 GEMM: A = h (fp16) ----
    {
        dim3 grid((kC2 + kC2) / 128, cdiv(N, 128));
        gemm_dual_tc<__half, true><<<grid, 256>>>(p_h, Wl2, bl2, (void*)p_xl2, kC2,
                                                  Wr2, br2, p_xr2, kC2, N, kHC1);
    }
    // ---- layer 2 fused edge phase -> out ----
    gat_fused_l2<<<cdiv(N * 32, T), T>>>(p_off, p_csr, p_xl2, p_xr2, att2, bias2, out, N);

    // ---- re-zero deg for the next replay ----
    zeroi<<<cdiv(N, T), T>>>(p_deg, N);
}

// round 16
// speedup vs baseline: 1.1906x; 1.0163x over previous
#include <cuda_runtime.h>
#include <cuda_fp16.h>
#include <cstddef>
#include <cstdint>

// ---------------- problem constants ----------------
constexpr int kMaxN  = 50016;
constexpr int kMaxE  = 400000;
constexpr int kMaxTE = kMaxN + kMaxE;
constexpr int kHC1   = 256;
constexpr int kC2    = 64;

// ---------------- device scratch ----------------
__device__ __half g_xh [(size_t)kMaxN * 128];    // x in fp16
__device__ __half g_w1h[(size_t)128 * 512];      // [Wl1|Wr1] fp16, width 512
__device__ __half g_w2h[(size_t)256 * 128];      // [Wl2|Wr2] fp16, width 128
__device__ __half g_xl1[(size_t)kMaxN * kHC1];
__device__ float  g_xr1[(size_t)kMaxN * kHC1];
__device__ __half g_h  [(size_t)kMaxN * kHC1];
__device__ __half g_xl2[(size_t)kMaxN * kC2];
__device__ float  g_xr2[(size_t)kMaxN * kC2];
__device__ int    g_deg[kMaxN];                  // zero-init at load; re-zeroed at graph end
__device__ int    g_off[kMaxN + 1];
__device__ int    g_cur[kMaxN];
__device__ int    g_bsum[128];
__device__ int    g_csr_src[kMaxTE];

// ---------------- small utility kernels ----------------
__global__ void zeroi(int* p, int n) {
    int i = blockIdx.x * blockDim.x + threadIdx.x;
    if (i < n) p[i] = 0;
}

// fp32 -> fp16, n multiple of 8
__global__ void cvt_f2h(const float* __restrict__ src, __half* __restrict__ dst, int n) {
    int i = blockIdx.x * blockDim.x + threadIdx.x;
    if (i * 8 >= n) return;
    float4 v0 = *(const float4*)(src + (size_t)i * 8);
    float4 v1 = *(const float4*)(src + (size_t)i * 8 + 4);
    uint4 w;
    __half2* wp = (__half2*)&w;
    wp[0] = __floats2half2_rn(v0.x, v0.y);
    wp[1] = __floats2half2_rn(v0.z, v0.w);
    wp[2] = __floats2half2_rn(v1.x, v1.y);
    wp[3] = __floats2half2_rn(v1.z, v1.w);
    *((uint4*)dst + i) = w;
}

// concat two fp32 weight matrices [K x n1], [K x n2] into fp16 [K x (n1+n2)]
__global__ void cvt_wcat(const float* __restrict__ B1, const float* __restrict__ B2,
                         __half* __restrict__ dst, int K, int n1, int n2) {
    int i = blockIdx.x * blockDim.x + threadIdx.x;
    int ncat = n1 + n2;
    if (i >= K * ncat) return;
    int k = i / ncat, c = i - k * ncat;
    float v = (c < n1) ? B1[(size_t)k * n1 + c] : B2[(size_t)k * n2 + (c - n1)];
    dst[i] = __float2half_rn(v);
}

__global__ void count_deg(const int* __restrict__ ei, int E, int TE, int* __restrict__ deg) {
    int i = blockIdx.x * blockDim.x + threadIdx.x;
    if (i >= TE) return;
    int d = (i < E) ? ei[E + i] : (i - E);
    atomicAdd(&deg[d], 1);
}

__global__ void scan_block(const int* __restrict__ deg, int* __restrict__ off,
                           int* __restrict__ bsum, int n) {
    __shared__ int sh[1024];
    int tid = threadIdx.x;
    int i = blockIdx.x * 1024 + tid;
    int v = (i < n) ? deg[i] : 0;
    sh[tid] = v;
    __syncthreads();
    for (int o = 1; o < 1024; o <<= 1) {
        int t = (tid >= o) ? sh[tid - o] : 0;
        __syncthreads();
        sh[tid] += t;
        __syncthreads();
    }
    if (i < n) off[i] = sh[tid] - v;
    if (tid == 1023) bsum[blockIdx.x] = sh[1023];
}

__global__ void scan_add2(int* __restrict__ off, const int* __restrict__ bsum,
                          int* __restrict__ cur, int n, int total, int nb) {
    __shared__ int sh[128];
    int tid = threadIdx.x;
    if (tid < 128) sh[tid] = (tid < nb) ? bsum[tid] : 0;
    __syncthreads();
    for (int o = 1; o < 128; o <<= 1) {
        int u = (tid >= o && tid < 128) ? sh[tid - o] : 0;
        __syncthreads();
        if (tid < 128) sh[tid] += u;
        __syncthreads();
    }
    int i = blockIdx.x * blockDim.x + tid;
    if (i < n) {
        int b = i >> 10;
        int add = (b == 0) ? 0 : sh[b - 1];
        int v = off[i] + add;
        off[i] = v;
        cur[i] = v;
    }
    if (i == 0) off[n] = total;
}

__global__ void scatter_csr(const int* __restrict__ ei, int E, int TE,
                            int* __restrict__ cur, int* __restrict__ csr_src) {
    int i = blockIdx.x * blockDim.x + threadIdx.x;
    if (i >= TE) return;
    int s, d;
    if (i < E) { s = ei[i]; d = ei[E + i]; }
    else       { s = i - E; d = s; }
    int pos = atomicAdd(&cur[d], 1);
    csr_src[pos] = s;
}

// ---------------- FP16 tensor-core dual-output GEMM ----------------
// C = A[MxK](fp16) @ Bc[Kx(n1+n2)](fp16) + bias, fp32 accumulate.
// Block 128x128, k-chunk 32, 8 warps (4M x 2N), warp tile 32x64.
// mma.m16n8k16; A fragments via ldmatrix.x4, B via ldmatrix.x4.trans.

__device__ __forceinline__ void mma_f16(float* d, const unsigned* a, unsigned b0, unsigned b1) {
    asm volatile(
        "mma.sync.aligned.m16n8k16.row.col.f32.f16.f16.f32 "
        "{%0,%1,%2,%3}, {%4,%5,%6,%7}, {%8,%9}, {%0,%1,%2,%3};"
        : "+f"(d[0]), "+f"(d[1]), "+f"(d[2]), "+f"(d[3])
        : "r"(a[0]), "r"(a[1]), "r"(a[2]), "r"(a[3]), "r"(b0), "r"(b1));
}

constexpr int kBStrW = 68;   // Bs row stride in 32-bit words (64 + 4 pad)

template <bool HALF1>
__global__ __launch_bounds__(256, 2)
void gemm_dual_tc(const __half* __restrict__ A, const __half* __restrict__ Bc,
                  const float* __restrict__ bias1, void* __restrict__ Cd1, int n1,
                  const float* __restrict__ bias2, float* __restrict__ Cd2, int n2,
                  int M, int K) {
    // As: [128 m][16 half2-words] with 4-word chunk XOR swizzle (chunk ^ ((r>>1)&3))
    // Bs: [32 k][64 half2-words + 4 pad] plain layout for ldmatrix
    __shared__ unsigned AsW[128 * 16];
    __shared__ unsigned BsW[32 * kBStrW];

    const int ncat = n1 + n2;
    const int tid  = threadIdx.x;
    const int lane = tid & 31;
    const int wid  = tid >> 5;
    const int wm   = (wid & 3) * 32;
    const int wn   = (wid >> 2) * 64;
    const int row0 = blockIdx.y * 128;
    const int col0 = blockIdx.x * 128;
    const int gr   = lane >> 2;
    const int kkw  = lane & 3;

    float d[2][8][4];
#pragma unroll
    for (int mi = 0; mi < 2; ++mi)
#pragma unroll
        for (int ni = 0; ni < 8; ++ni)
#pragma unroll
            for (int r = 0; r < 4; ++r) d[mi][ni][r] = 0.f;

    const int a_row = tid >> 2;        // 0..63
    const int a_k8  = (tid & 3) * 8;   // half index within the 32-k chunk
    const int b_row = tid >> 4;        // 0..15
    const int b_c8  = (tid & 15) * 8;  // half col within 128-wide tile

    const uint32_t bSm = (uint32_t)__cvta_generic_to_shared(BsW);
    const uint32_t bLaneBase = bSm
        + (uint32_t)((((lane & 15) * kBStrW) + (wn >> 1) + ((lane >> 4) * 4)) * 4);

    const uint32_t aSm = (uint32_t)__cvta_generic_to_shared(AsW);
    const int lj  = lane >> 3;          // matrix index 0..3
    const int lhi = lane >> 4;          // chunk high bit (k8 group)
    const int ar0 = wm + ((lj & 1) << 3) + (lane & 7);   // row for mi=0
    const int ar1 = ar0 + 16;                            // row for mi=1
    const uint32_t aBase0 = aSm + (uint32_t)(ar0 * 64);
    const uint32_t aBase1 = aSm + (uint32_t)(ar1 * 64);
    const int aswz0 = (ar0 >> 1) & 3;
    const int aswz1 = (ar1 >> 1) & 3;

    for (int k0 = 0; k0 < K; k0 += 32) {
        // ---- A tile (128 x 32 halfs): direct fp16 LDG.128 -> swizzled STS.128 ----
#pragma unroll
        for (int p = 0; p < 2; ++p) {
            int r = p * 64 + a_row;
            uint4 w = make_uint4(0u, 0u, 0u, 0u);
            if (row0 + r < M)
                w = *(const uint4*)(A + (size_t)(row0 + r) * K + k0 + a_k8);
            int chunk = (tid & 3) ^ ((r >> 1) & 3);
            *(uint4*)(AsW + r * 16 + chunk * 4) = w;
        }
        // ---- B tile (32 x 128 halfs): direct fp16 LDG.128 -> STS.128 ----
#pragma unroll
        for (int p = 0; p < 2; ++p) {
            int kk = p * 16 + b_row;
            uint4 w = *(const uint4*)(Bc + (size_t)(k0 + kk) * ncat + col0 + b_c8);
            *(uint4*)(BsW + kk * kBStrW + (b_c8 >> 1)) = w;
        }
        __syncthreads();

#pragma unroll
        for (int k16 = 0; k16 < 2; ++k16) {
            unsigned a[2][4];
            int ch = k16 * 2 + lhi;
            uint32_t ad0 = aBase0 + (uint32_t)(((ch ^ aswz0) << 4));
            uint32_t ad1 = aBase1 + (uint32_t)(((ch ^ aswz1) << 4));
            asm volatile(
                "ldmatrix.sync.aligned.m8n8.x4.shared.b16 {%0,%1,%2,%3}, [%4];"
                : "=r"(a[0][0]), "=r"(a[0][1]), "=r"(a[0][2]), "=r"(a[0][3])
                : "r"(ad0));
            asm volatile(
                "ldmatrix.sync.aligned.m8n8.x4.shared.b16 {%0,%1,%2,%3}, [%4];"
                : "=r"(a[1][0]), "=r"(a[1][1]), "=r"(a[1][2]), "=r"(a[1][3])
                : "r"(ad1));

            uint32_t bAddr = bLaneBase + (uint32_t)(k16 * 16 * kBStrW * 4);
#pragma unroll
            for (int ni2 = 0; ni2 < 4; ++ni2) {
                unsigned b0, b1, b2, b3;
                asm volatile(
                    "ldmatrix.sync.aligned.m8n8.x4.trans.shared.b16 {%0,%1,%2,%3}, [%4];"
                    : "=r"(b0), "=r"(b1), "=r"(b2), "=r"(b3)
                    : "r"(bAddr + (uint32_t)(ni2 * 32)));
                mma_f16(d[0][ni2 * 2 + 0], a[0], b0, b1);
                mma_f16(d[1][ni2 * 2 + 0], a[1], b0, b1);
                mma_f16(d[0][ni2 * 2 + 1], a[0], b2, b3);
                mma_f16(d[1][ni2 * 2 + 1], a[1], b2, b3);
            }
        }
        __syncthreads();
    }

    const bool isOut1 = (col0 + wn < n1);
    const float* bias = isOut1 ? bias1 : bias2;
    const int Nc      = isOut1 ? n1 : n2;
    const int cbase   = isOut1 ? (col0 + wn) : (col0 + wn - n1);

#pragma unroll
    for (int mi = 0; mi < 2; ++mi) {
#pragma unroll
        for (int half = 0; half < 2; ++half) {
            int r = row0 + wm + mi * 16 + gr + half * 8;
            if (r >= M) continue;
#pragma unroll
            for (int ni = 0; ni < 8; ++ni) {
                int c = cbase + ni * 8 + 2 * kkw;
                float vx = d[mi][ni][half * 2 + 0] + __ldg(bias + c + 0);
                float vy = d[mi][ni][half * 2 + 1] + __ldg(bias + c + 1);
                if (isOut1) {
                    if (HALF1) {
                        __half* Co = (__half*)Cd1;
                        *(__half2*)(Co + (size_t)r * Nc + c) = __floats2half2_rn(vx, vy);
                    } else {
                        float* Co = (float*)Cd1;
                        *(float2*)(Co + (size_t)r * Nc + c) = make_float2(vx, vy);
                    }
                } else {
                    *(float2*)(Cd2 + (size_t)r * Nc + c) = make_float2(vx, vy);
                }
            }
        }
    }
}

// ---------------- helpers ----------------
__device__ __forceinline__ float leaky(float t) { return fmaxf(t, 0.2f * t); }

// ---------------- layer-1 fused edge phase (H=4, C=64, +bias +elu, fp16 out) ----
__global__ void gat_fused_l1(const int* __restrict__ off, const int* __restrict__ csr,
                             const __half* __restrict__ xl, const float* __restrict__ xr,
                             const float* __restrict__ att, const float* __restrict__ bias,
                             __half* __restrict__ out, int N) {
    int node = (blockIdx.x * blockDim.x + threadIdx.x) >> 5;
    if (node >= N) return;
    int lane = threadIdx.x & 31;

    const float4* prx = (const float4*)(xr + (size_t)node * 256);
    float4 xra = __ldg(prx + lane * 2);
    float4 xrb = __ldg(prx + lane * 2 + 1);
    const float4* pat = (const float4*)att;
    float4 ata = __ldg(pat + lane * 2);
    float4 atb = __ldg(pat + lane * 2 + 1);

    float acc[8];
#pragma unroll
    for (int i = 0; i < 8; ++i) acc[i] = 0.f;
    float m = -1e30f, s = 0.f;

    int e0 = __ldg(off + node), e1 = __ldg(off + node + 1);
#pragma unroll 2
    for (int e = e0; e < e1; ++e) {
        int src = __ldg(csr + e);
        uint4 u = __ldg((const uint4*)(xl + (size_t)src * 256) + lane);
        const __half2* hp = (const __half2*)&u;
        float2 f0 = __half22float2(hp[0]);
        float2 f1 = __half22float2(hp[1]);
        float2 f2 = __half22float2(hp[2]);
        float2 f3 = __half22float2(hp[3]);
        float v[8] = {f0.x, f0.y, f1.x, f1.y, f2.x, f2.y, f3.x, f3.y};

        float q = leaky(v[0] + xra.x) * ata.x;
        q = fmaf(leaky(v[1] + xra.y), ata.y, q);
        q = fmaf(leaky(v[2] + xra.z), ata.z, q);
        q = fmaf(leaky(v[3] + xra.w), ata.w, q);
        q = fmaf(leaky(v[4] + xrb.x), atb.x, q);
        q = fmaf(leaky(v[5] + xrb.y), atb.y, q);
        q = fmaf(leaky(v[6] + xrb.z), atb.z, q);
        q = fmaf(leaky(v[7] + xrb.w), atb.w, q);

        q += __shfl_xor_sync(0xffffffffu, q, 4);
        q += __shfl_xor_sync(0xffffffffu, q, 2);
        q += __shfl_xor_sync(0xffffffffu, q, 1);

        float nm = fmaxf(m, q);
        float sc = __expf(m - nm);
        float w  = __expf(q - nm);
        s = s * sc + w;
        m = nm;
#pragma unroll
        for (int i = 0; i < 8; ++i) acc[i] = fmaf(acc[i], sc, w * v[i]);
    }

    float inv = 1.f / s;
    const float4* pb = (const float4*)bias;
    float4 b0 = __ldg(pb + lane * 2), b1 = __ldg(pb + lane * 2 + 1);
    float o[8];
    o[0] = acc[0] * inv + b0.x;  o[1] = acc[1] * inv + b0.y;
    o[2] = acc[2] * inv + b0.z;  o[3] = acc[3] * inv + b0.w;
    o[4] = acc[4] * inv + b1.x;  o[5] = acc[5] * inv + b1.y;
    o[6] = acc[6] * inv + b1.z;  o[7] = acc[7] * inv + b1.w;
#pragma unroll
    for (int i = 0; i < 8; ++i) o[i] = (o[i] > 0.f) ? o[i] : expm1f(o[i]);

    uint4 w;
    __half2* wp = (__half2*)&w;
    wp[0] = __floats2half2_rn(o[0], o[1]);
    wp[1] = __floats2half2_rn(o[2], o[3]);
    wp[2] = __floats2half2_rn(o[4], o[5]);
    wp[3] = __floats2half2_rn(o[6], o[7]);
    *((uint4*)(out + (size_t)node * 256) + lane) = w;
}

// ---------------- layer-2 fused edge phase (H=1, C=64, +bias) ----------------
__global__ void gat_fused_l2(const int* __restrict__ off, const int* __restrict__ csr,
                             const __half* __restrict__ xl, const float* __restrict__ xr,
                             const float* __restrict__ att, const float* __restrict__ bias,
                             float* __restrict__ out, int N) {
    int node = (blockIdx.x * blockDim.x + threadIdx.x) >> 5;
    if (node >= N) return;
    int lane = threadIdx.x & 31;

    float2 xrv = __ldg((const float2*)(xr + (size_t)node * 64) + lane);
    float2 atv = __ldg((const float2*)att + lane);

    float2 acc = make_float2(0.f, 0.f);
    float m = -1e30f, s = 0.f;

    int e0 = __ldg(off + node), e1 = __ldg(off + node + 1);
#pragma unroll 2
    for (int e = e0; e < e1; ++e) {
        int src = __ldg(csr + e);
        __half2 hv = __ldg((const __half2*)(xl + (size_t)src * 64) + lane);
        float2 v = __half22float2(hv);
        float q = leaky(v.x + xrv.x) * atv.x;
        q = fmaf(leaky(v.y + xrv.y), atv.y, q);
#pragma unroll
        for (int o = 16; o; o >>= 1) q += __shfl_xor_sync(0xffffffffu, q, o);
        float nm = fmaxf(m, q);
        float sc = __expf(m - nm);
        float w  = __expf(q - nm);
        s = s * sc + w;
        m = nm;
        acc.x = fmaf(acc.x, sc, w * v.x);
        acc.y = fmaf(acc.y, sc, w * v.y);
    }

    float inv = 1.f / s;
    float2 bv = __ldg((const float2*)bias + lane);
    float2 o;
    o.x = acc.x * inv + bv.x;
    o.y = acc.y * inv + bv.y;
    *((float2*)(out + (size_t)node * 64) + lane) = o;
}

// ---------------- host launch ----------------
static __half* p_xh  = nullptr;
static __half* p_w1h = nullptr;
static __half* p_w2h = nullptr;
static __half* p_xl1 = nullptr;
static float*  p_xr1 = nullptr;
static __half* p_h   = nullptr;
static __half* p_xl2 = nullptr;
static float*  p_xr2 = nullptr;
static int*    p_deg = nullptr;
static int*    p_off = nullptr;
static int*    p_cur = nullptr;
static int*    p_bsum = nullptr;
static int*    p_csr = nullptr;
static cudaStream_t s_side = nullptr;
static cudaEvent_t  s_fork = nullptr, s_join = nullptr;

extern "C" void kernel_launch(void* const* d_in, const int* in_sizes, int n_in,
                              void* d_out, int out_size) {
    if (!p_xl1) {
        void* p;
        cudaGetSymbolAddress(&p, g_xh);      p_xh  = (__half*)p;
        cudaGetSymbolAddress(&p, g_w1h);     p_w1h = (__half*)p;
        cudaGetSymbolAddress(&p, g_w2h);     p_w2h = (__half*)p;
        cudaGetSymbolAddress(&p, g_xl1);     p_xl1 = (__half*)p;
        cudaGetSymbolAddress(&p, g_xr1);     p_xr1 = (float*)p;
        cudaGetSymbolAddress(&p, g_h);       p_h   = (__half*)p;
        cudaGetSymbolAddress(&p, g_xl2);     p_xl2 = (__half*)p;
        cudaGetSymbolAddress(&p, g_xr2);     p_xr2 = (float*)p;
        cudaGetSymbolAddress(&p, g_deg);     p_deg = (int*)p;
        cudaGetSymbolAddress(&p, g_off);     p_off = (int*)p;
        cudaGetSymbolAddress(&p, g_cur);     p_cur = (int*)p;
        cudaGetSymbolAddress(&p, g_bsum);    p_bsum = (int*)p;
        cudaGetSymbolAddress(&p, g_csr_src); p_csr = (int*)p;
        cudaStreamCreateWithFlags(&s_side, cudaStreamNonBlocking);
        cudaEventCreateWithFlags(&s_fork, cudaEventDisableTiming);
        cudaEventCreateWithFlags(&s_join, cudaEventDisableTiming);
    }

    const float* x     = (const float*)d_in[0];
    const int*   ei    = (const int*)d_in[1];
    const float* Wl1   = (const float*)d_in[2];
    const float* bl1   = (const float*)d_in[3];
    const float* Wr1   = (const float*)d_in[4];
    const float* br1   = (const float*)d_in[5];
    const float* att1  = (const float*)d_in[6];
    const float* bias1 = (const float*)d_in[7];
    const float* Wl2   = (const float*)d_in[8];
    const float* bl2   = (const float*)d_in[9];
    const float* Wr2   = (const float*)d_in[10];
    const float* br2   = (const float*)d_in[11];
    const float* att2  = (const float*)d_in[12];
    const float* bias2 = (const float*)d_in[13];
    float* out = (float*)d_out;

    const int IN = 128;
    const int N  = in_sizes[0] / IN;
    const int E  = in_sizes[1] / 2;
    const int TE = E + N;

    const int T = 256;
    auto cdiv = [](int a, int b) { return (a + b - 1) / b; };
    int nb = cdiv(N, 1024);

    // ---- fork event first so side-stream CSR overlaps converts + gemm1 ----
    cudaEventRecord(s_fork, 0);
    cudaStreamWaitEvent(s_side, s_fork, 0);

    // ---- main: fp16 pre-conversion (launches 1-3) ----
    cvt_f2h<<<cdiv(N * IN / 8, T), T>>>(x, p_xh, N * IN);                       // 1
    cvt_wcat<<<cdiv(128 * 512, T), T>>>(Wl1, Wr1, p_w1h, 128, kHC1, kHC1);      // 2
    cvt_wcat<<<cdiv(256 * 128, T), T>>>(Wl2, Wr2, p_w2h, 256, kC2, kC2);        // 3

    // ---- layer 1 GEMM (launch 4: ncu window) ----
    {
        dim3 grid((kHC1 + kHC1) / 128, cdiv(N, 128));
        gemm_dual_tc<true><<<grid, 256>>>(p_xh, p_w1h, bl1, (void*)p_xl1, kHC1,
                                          br1, p_xr1, kHC1, N, IN);
    }

    // ---- side: CSR build (launches 5-8), overlapped ----
    count_deg<<<cdiv(TE, T), T, 0, s_side>>>(ei, E, TE, p_deg);
    scan_block<<<nb, 1024, 0, s_side>>>(p_deg, p_off, p_bsum, N);
    scan_add2<<<cdiv(N, T), T, 0, s_side>>>(p_off, p_bsum, p_cur, N, TE, nb);
    scatter_csr<<<cdiv(TE, T), T, 0, s_side>>>(ei, E, TE, p_cur, p_csr);
    cudaEventRecord(s_join, s_side);

    // ---- join, then fused edge phase layer 1 -> h (fp16) ----
    cudaStreamWaitEvent(0, s_join, 0);
    gat_fused_l1<<<cdiv(N * 32, T), T>>>(p_off, p_csr, p_xl1, p_xr1, att1, bias1, p_h, N);

    // ---- layer 2 GEMM ----
    {
        dim3 grid((kC2 + kC2) / 128, cdiv(N, 128));
        gemm_dual_tc<true><<<grid, 256>>>(p_h, p_w2h, bl2, (void*)p_xl2, kC2,
                                          br2, p_xr2, kC2, N, kHC1);
    }
    // ---- layer 2 fused edge phase -> out ----
    gat_fused_l2<<<cdiv(N * 32, T), T>>>(p_off, p_csr, p_xl2, p_xr2, att2, bias2, out, N);

    // ---- re-zero deg for the next replay ----
    zeroi<<<cdiv(N, T), T>>>(p_deg, N);
}

// round 17
// speedup vs baseline: 1.2284x; 1.0318x over previous
#include <cuda_runtime.h>
#include <cuda_fp16.h>
#include <cstddef>
#include <cstdint>

// ---------------- problem constants ----------------
constexpr int kMaxN  = 50016;
constexpr int kMaxE  = 400000;
constexpr int kMaxTE = kMaxN + kMaxE;
constexpr int kHC1   = 256;
constexpr int kC2    = 64;

// ---------------- device scratch ----------------
__device__ __half g_xh [(size_t)kMaxN * 128];    // x in fp16
__device__ __half g_w1h[(size_t)128 * 512];      // [Wl1|Wr1] fp16
__device__ __half g_w2h[(size_t)256 * 128];      // [Wl2|Wr2] fp16
__device__ __half g_xl1[(size_t)kMaxN * kHC1];
__device__ float  g_xr1[(size_t)kMaxN * kHC1];
__device__ __half g_h  [(size_t)kMaxN * kHC1];
__device__ __half g_xl2[(size_t)kMaxN * kC2];
__device__ float  g_xr2[(size_t)kMaxN * kC2];
__device__ int    g_deg[kMaxN];                  // zero-init at load; re-zeroed at graph end
__device__ int    g_off[kMaxN + 1];
__device__ int    g_cur[kMaxN];
__device__ int    g_bsum[128];
__device__ int    g_csr_src[kMaxTE];

// ---------------- small utility kernels ----------------
__global__ void zeroi(int* p, int n) {
    int i = blockIdx.x * blockDim.x + threadIdx.x;
    if (i < n) p[i] = 0;
}

__global__ void cvt_f2h(const float* __restrict__ src, __half* __restrict__ dst, int n) {
    int i = blockIdx.x * blockDim.x + threadIdx.x;
    if (i * 8 >= n) return;
    float4 v0 = *(const float4*)(src + (size_t)i * 8);
    float4 v1 = *(const float4*)(src + (size_t)i * 8 + 4);
    uint4 w;
    __half2* wp = (__half2*)&w;
    wp[0] = __floats2half2_rn(v0.x, v0.y);
    wp[1] = __floats2half2_rn(v0.z, v0.w);
    wp[2] = __floats2half2_rn(v1.x, v1.y);
    wp[3] = __floats2half2_rn(v1.z, v1.w);
    *((uint4*)dst + i) = w;
}

__global__ void cvt_wcat(const float* __restrict__ B1, const float* __restrict__ B2,
                         __half* __restrict__ dst, int K, int n1, int n2) {
    int i = blockIdx.x * blockDim.x + threadIdx.x;
    int ncat = n1 + n2;
    if (i >= K * ncat) return;
    int k = i / ncat, c = i - k * ncat;
    float v = (c < n1) ? B1[(size_t)k * n1 + c] : B2[(size_t)k * n2 + (c - n1)];
    dst[i] = __float2half_rn(v);
}

__global__ void count_deg(const int* __restrict__ ei, int E, int TE, int* __restrict__ deg) {
    int i = blockIdx.x * blockDim.x + threadIdx.x;
    if (i >= TE) return;
    int d = (i < E) ? ei[E + i] : (i - E);
    atomicAdd(&deg[d], 1);
}

__global__ void scan_block(const int* __restrict__ deg, int* __restrict__ off,
                           int* __restrict__ bsum, int n) {
    __shared__ int sh[1024];
    int tid = threadIdx.x;
    int i = blockIdx.x * 1024 + tid;
    int v = (i < n) ? deg[i] : 0;
    sh[tid] = v;
    __syncthreads();
    for (int o = 1; o < 1024; o <<= 1) {
        int t = (tid >= o) ? sh[tid - o] : 0;
        __syncthreads();
        sh[tid] += t;
        __syncthreads();
    }
    if (i < n) off[i] = sh[tid] - v;
    if (tid == 1023) bsum[blockIdx.x] = sh[1023];
}

__global__ void scan_add2(int* __restrict__ off, const int* __restrict__ bsum,
                          int* __restrict__ cur, int n, int total, int nb) {
    __shared__ int sh[128];
    int tid = threadIdx.x;
    if (tid < 128) sh[tid] = (tid < nb) ? bsum[tid] : 0;
    __syncthreads();
    for (int o = 1; o < 128; o <<= 1) {
        int u = (tid >= o && tid < 128) ? sh[tid - o] : 0;
        __syncthreads();
        if (tid < 128) sh[tid] += u;
        __syncthreads();
    }
    int i = blockIdx.x * blockDim.x + tid;
    if (i < n) {
        int b = i >> 10;
        int add = (b == 0) ? 0 : sh[b - 1];
        int v = off[i] + add;
        off[i] = v;
        cur[i] = v;
    }
    if (i == 0) off[n] = total;
}

__global__ void scatter_csr(const int* __restrict__ ei, int E, int TE,
                            int* __restrict__ cur, int* __restrict__ csr_src) {
    int i = blockIdx.x * blockDim.x + threadIdx.x;
    if (i >= TE) return;
    int s, d;
    if (i < E) { s = ei[i]; d = ei[E + i]; }
    else       { s = i - E; d = s; }
    int pos = atomicAdd(&cur[d], 1);
    csr_src[pos] = s;
}

// ---------------- FP16 tensor-core dual-output GEMM (unchanged from R16) ------
__device__ __forceinline__ void mma_f16(float* d, const unsigned* a, unsigned b0, unsigned b1) {
    asm volatile(
        "mma.sync.aligned.m16n8k16.row.col.f32.f16.f16.f32 "
        "{%0,%1,%2,%3}, {%4,%5,%6,%7}, {%8,%9}, {%0,%1,%2,%3};"
        : "+f"(d[0]), "+f"(d[1]), "+f"(d[2]), "+f"(d[3])
        : "r"(a[0]), "r"(a[1]), "r"(a[2]), "r"(a[3]), "r"(b0), "r"(b1));
}

constexpr int kBStrW = 68;

template <bool HALF1>
__global__ __launch_bounds__(256, 2)
void gemm_dual_tc(const __half* __restrict__ A, const __half* __restrict__ Bc,
                  const float* __restrict__ bias1, void* __restrict__ Cd1, int n1,
                  const float* __restrict__ bias2, float* __restrict__ Cd2, int n2,
                  int M, int K) {
    __shared__ unsigned AsW[128 * 16];
    __shared__ unsigned BsW[32 * kBStrW];

    const int ncat = n1 + n2;
    const int tid  = threadIdx.x;
    const int lane = tid & 31;
    const int wid  = tid >> 5;
    const int wm   = (wid & 3) * 32;
    const int wn   = (wid >> 2) * 64;
    const int row0 = blockIdx.y * 128;
    const int col0 = blockIdx.x * 128;
    const int gr   = lane >> 2;
    const int kkw  = lane & 3;

    float d[2][8][4];
#pragma unroll
    for (int mi = 0; mi < 2; ++mi)
#pragma unroll
        for (int ni = 0; ni < 8; ++ni)
#pragma unroll
            for (int r = 0; r < 4; ++r) d[mi][ni][r] = 0.f;

    const int a_row = tid >> 2;
    const int a_k8  = (tid & 3) * 8;
    const int b_row = tid >> 4;
    const int b_c8  = (tid & 15) * 8;

    const uint32_t bSm = (uint32_t)__cvta_generic_to_shared(BsW);
    const uint32_t bLaneBase = bSm
        + (uint32_t)((((lane & 15) * kBStrW) + (wn >> 1) + ((lane >> 4) * 4)) * 4);

    const uint32_t aSm = (uint32_t)__cvta_generic_to_shared(AsW);
    const int lj  = lane >> 3;
    const int lhi = lane >> 4;
    const int ar0 = wm + ((lj & 1) << 3) + (lane & 7);
    const int ar1 = ar0 + 16;
    const uint32_t aBase0 = aSm + (uint32_t)(ar0 * 64);
    const uint32_t aBase1 = aSm + (uint32_t)(ar1 * 64);
    const int aswz0 = (ar0 >> 1) & 3;
    const int aswz1 = (ar1 >> 1) & 3;

    for (int k0 = 0; k0 < K; k0 += 32) {
#pragma unroll
        for (int p = 0; p < 2; ++p) {
            int r = p * 64 + a_row;
            uint4 w = make_uint4(0u, 0u, 0u, 0u);
            if (row0 + r < M)
                w = *(const uint4*)(A + (size_t)(row0 + r) * K + k0 + a_k8);
            int chunk = (tid & 3) ^ ((r >> 1) & 3);
            *(uint4*)(AsW + r * 16 + chunk * 4) = w;
        }
#pragma unroll
        for (int p = 0; p < 2; ++p) {
            int kk = p * 16 + b_row;
            uint4 w = *(const uint4*)(Bc + (size_t)(k0 + kk) * ncat + col0 + b_c8);
            *(uint4*)(BsW + kk * kBStrW + (b_c8 >> 1)) = w;
        }
        __syncthreads();

#pragma unroll
        for (int k16 = 0; k16 < 2; ++k16) {
            unsigned a[2][4];
            int ch = k16 * 2 + lhi;
            uint32_t ad0 = aBase0 + (uint32_t)(((ch ^ aswz0) << 4));
            uint32_t ad1 = aBase1 + (uint32_t)(((ch ^ aswz1) << 4));
            asm volatile(
                "ldmatrix.sync.aligned.m8n8.x4.shared.b16 {%0,%1,%2,%3}, [%4];"
                : "=r"(a[0][0]), "=r"(a[0][1]), "=r"(a[0][2]), "=r"(a[0][3])
                : "r"(ad0));
            asm volatile(
                "ldmatrix.sync.aligned.m8n8.x4.shared.b16 {%0,%1,%2,%3}, [%4];"
                : "=r"(a[1][0]), "=r"(a[1][1]), "=r"(a[1][2]), "=r"(a[1][3])
                : "r"(ad1));

            uint32_t bAddr = bLaneBase + (uint32_t)(k16 * 16 * kBStrW * 4);
#pragma unroll
            for (int ni2 = 0; ni2 < 4; ++ni2) {
                unsigned b0, b1, b2, b3;
                asm volatile(
                    "ldmatrix.sync.aligned.m8n8.x4.trans.shared.b16 {%0,%1,%2,%3}, [%4];"
                    : "=r"(b0), "=r"(b1), "=r"(b2), "=r"(b3)
                    : "r"(bAddr + (uint32_t)(ni2 * 32)));
                mma_f16(d[0][ni2 * 2 + 0], a[0], b0, b1);
                mma_f16(d[1][ni2 * 2 + 0], a[1], b0, b1);
                mma_f16(d[0][ni2 * 2 + 1], a[0], b2, b3);
                mma_f16(d[1][ni2 * 2 + 1], a[1], b2, b3);
            }
        }
        __syncthreads();
    }

    const bool isOut1 = (col0 + wn < n1);
    const float* bias = isOut1 ? bias1 : bias2;
    const int Nc      = isOut1 ? n1 : n2;
    const int cbase   = isOut1 ? (col0 + wn) : (col0 + wn - n1);

#pragma unroll
    for (int mi = 0; mi < 2; ++mi) {
#pragma unroll
        for (int half = 0; half < 2; ++half) {
            int r = row0 + wm + mi * 16 + gr + half * 8;
            if (r >= M) continue;
#pragma unroll
            for (int ni = 0; ni < 8; ++ni) {
                int c = cbase + ni * 8 + 2 * kkw;
                float vx = d[mi][ni][half * 2 + 0] + __ldg(bias + c + 0);
                float vy = d[mi][ni][half * 2 + 1] + __ldg(bias + c + 1);
                if (isOut1) {
                    if (HALF1) {
                        __half* Co = (__half*)Cd1;
                        *(__half2*)(Co + (size_t)r * Nc + c) = __floats2half2_rn(vx, vy);
                    } else {
                        float* Co = (float*)Cd1;
                        *(float2*)(Co + (size_t)r * Nc + c) = make_float2(vx, vy);
                    }
                } else {
                    *(float2*)(Cd2 + (size_t)r * Nc + c) = make_float2(vx, vy);
                }
            }
        }
    }
}

// ---------------- helpers ----------------
__device__ __forceinline__ float leaky(float t) { return fmaxf(t, 0.2f * t); }

// ---------------- layer-1 fused edge phase (pair-pipelined gathers) ----------
__global__ void gat_fused_l1(const int* __restrict__ off, const int* __restrict__ csr,
                             const __half* __restrict__ xl, const float* __restrict__ xr,
                             const float* __restrict__ att, const float* __restrict__ bias,
                             __half* __restrict__ out, int N) {
    int node = (blockIdx.x * blockDim.x + threadIdx.x) >> 5;
    if (node >= N) return;
    int lane = threadIdx.x & 31;

    const float4* prx = (const float4*)(xr + (size_t)node * 256);
    float4 xra = __ldg(prx + lane * 2);
    float4 xrb = __ldg(prx + lane * 2 + 1);
    const float4* pat = (const float4*)att;
    float4 ata = __ldg(pat + lane * 2);
    float4 atb = __ldg(pat + lane * 2 + 1);

    float acc[8];
#pragma unroll
    for (int i = 0; i < 8; ++i) acc[i] = 0.f;
    float m = -1e30f, s = 0.f;

    auto process = [&](uint4 u) {
        const __half2* hp = (const __half2*)&u;
        float2 f0 = __half22float2(hp[0]);
        float2 f1 = __half22float2(hp[1]);
        float2 f2 = __half22float2(hp[2]);
        float2 f3 = __half22float2(hp[3]);
        float v[8] = {f0.x, f0.y, f1.x, f1.y, f2.x, f2.y, f3.x, f3.y};

        float q = leaky(v[0] + xra.x) * ata.x;
        q = fmaf(leaky(v[1] + xra.y), ata.y, q);
        q = fmaf(leaky(v[2] + xra.z), ata.z, q);
        q = fmaf(leaky(v[3] + xra.w), ata.w, q);
        q = fmaf(leaky(v[4] + xrb.x), atb.x, q);
        q = fmaf(leaky(v[5] + xrb.y), atb.y, q);
        q = fmaf(leaky(v[6] + xrb.z), atb.z, q);
        q = fmaf(leaky(v[7] + xrb.w), atb.w, q);

        q += __shfl_xor_sync(0xffffffffu, q, 4);
        q += __shfl_xor_sync(0xffffffffu, q, 2);
        q += __shfl_xor_sync(0xffffffffu, q, 1);

        float nm = fmaxf(m, q);
        float sc = __expf(m - nm);
        float w  = __expf(q - nm);
        s = s * sc + w;
        m = nm;
#pragma unroll
        for (int i = 0; i < 8; ++i) acc[i] = fmaf(acc[i], sc, w * v[i]);
    };

    auto gather = [&](int e) -> uint4 {
        int src = __ldg(csr + e);
        return __ldg((const uint4*)(xl + (size_t)src * 256) + lane);
    };

    int e0 = __ldg(off + node), e1 = __ldg(off + node + 1);
    int n = e1 - e0;
    uint4 a0, a1;
    if (n > 0) a0 = gather(e0);
    if (n > 1) a1 = gather(e0 + 1);
    int i = 0;
    while (i < n) {
        uint4 c0 = a0, c1 = a1;
        int j = i + 2;
        if (j     < n) a0 = gather(e0 + j);
        if (j + 1 < n) a1 = gather(e0 + j + 1);
        process(c0);
        if (i + 1 < n) process(c1);
        i = j;
    }

    float inv = 1.f / s;
    const float4* pb = (const float4*)bias;
    float4 b0 = __ldg(pb + lane * 2), b1 = __ldg(pb + lane * 2 + 1);
    float o[8];
    o[0] = acc[0] * inv + b0.x;  o[1] = acc[1] * inv + b0.y;
    o[2] = acc[2] * inv + b0.z;  o[3] = acc[3] * inv + b0.w;
    o[4] = acc[4] * inv + b1.x;  o[5] = acc[5] * inv + b1.y;
    o[6] = acc[6] * inv + b1.z;  o[7] = acc[7] * inv + b1.w;
#pragma unroll
    for (int i2 = 0; i2 < 8; ++i2) o[i2] = (o[i2] > 0.f) ? o[i2] : expm1f(o[i2]);

    uint4 w;
    __half2* wp = (__half2*)&w;
    wp[0] = __floats2half2_rn(o[0], o[1]);
    wp[1] = __floats2half2_rn(o[2], o[3]);
    wp[2] = __floats2half2_rn(o[4], o[5]);
    wp[3] = __floats2half2_rn(o[6], o[7]);
    *((uint4*)(out + (size_t)node * 256) + lane) = w;
}

// ---------------- layer-2 fused edge phase (quad-pipelined gathers) ----------
__global__ void gat_fused_l2(const int* __restrict__ off, const int* __restrict__ csr,
                             const __half* __restrict__ xl, const float* __restrict__ xr,
                             const float* __restrict__ att, const float* __restrict__ bias,
                             float* __restrict__ out, int N) {
    int node = (blockIdx.x * blockDim.x + threadIdx.x) >> 5;
    if (node >= N) return;
    int lane = threadIdx.x & 31;

    float2 xrv = __ldg((const float2*)(xr + (size_t)node * 64) + lane);
    float2 atv = __ldg((const float2*)att + lane);

    float2 acc = make_float2(0.f, 0.f);
    float m = -1e30f, s = 0.f;

    auto process = [&](__half2 hv) {
        float2 v = __half22float2(hv);
        float q = leaky(v.x + xrv.x) * atv.x;
        q = fmaf(leaky(v.y + xrv.y), atv.y, q);
#pragma unroll
        for (int o = 16; o; o >>= 1) q += __shfl_xor_sync(0xffffffffu, q, o);
        float nm = fmaxf(m, q);
        float sc = __expf(m - nm);
        float w  = __expf(q - nm);
        s = s * sc + w;
        m = nm;
        acc.x = fmaf(acc.x, sc, w * v.x);
        acc.y = fmaf(acc.y, sc, w * v.y);
    };

    auto gather = [&](int e) -> __half2 {
        int src = __ldg(csr + e);
        return __ldg((const __half2*)(xl + (size_t)src * 64) + lane);
    };

    int e0 = __ldg(off + node), e1 = __ldg(off + node + 1);
    int n = e1 - e0;
    __half2 a0, a1, a2, a3;
    if (n > 0) a0 = gather(e0);
    if (n > 1) a1 = gather(e0 + 1);
    if (n > 2) a2 = gather(e0 + 2);
    if (n > 3) a3 = gather(e0 + 3);
    int i = 0;
    while (i < n) {
        __half2 c0 = a0, c1 = a1, c2 = a2, c3 = a3;
        int j = i + 4;
        if (j     < n) a0 = gather(e0 + j);
        if (j + 1 < n) a1 = gather(e0 + j + 1);
        if (j + 2 < n) a2 = gather(e0 + j + 2);
        if (j + 3 < n) a3 = gather(e0 + j + 3);
        process(c0);
        if (i + 1 < n) process(c1);
        if (i + 2 < n) process(c2);
        if (i + 3 < n) process(c3);
        i = j;
    }

    float inv = 1.f / s;
    float2 bv = __ldg((const float2*)bias + lane);
    float2 o;
    o.x = acc.x * inv + bv.x;
    o.y = acc.y * inv + bv.y;
    *((float2*)(out + (size_t)node * 64) + lane) = o;
}

// ---------------- host launch ----------------
static __half* p_xh  = nullptr;
static __half* p_w1h = nullptr;
static __half* p_w2h = nullptr;
static __half* p_xl1 = nullptr;
static float*  p_xr1 = nullptr;
static __half* p_h   = nullptr;
static __half* p_xl2 = nullptr;
static float*  p_xr2 = nullptr;
static int*    p_deg = nullptr;
static int*    p_off = nullptr;
static int*    p_cur = nullptr;
static int*    p_bsum = nullptr;
static int*    p_csr = nullptr;
static cudaStream_t s_side = nullptr;
static cudaEvent_t  s_fork = nullptr, s_join = nullptr;

extern "C" void kernel_launch(void* const* d_in, const int* in_sizes, int n_in,
                              void* d_out, int out_size) {
    if (!p_xl1) {
        void* p;
        cudaGetSymbolAddress(&p, g_xh);      p_xh  = (__half*)p;
        cudaGetSymbolAddress(&p, g_w1h);     p_w1h = (__half*)p;
        cudaGetSymbolAddress(&p, g_w2h);     p_w2h = (__half*)p;
        cudaGetSymbolAddress(&p, g_xl1);     p_xl1 = (__half*)p;
        cudaGetSymbolAddress(&p, g_xr1);     p_xr1 = (float*)p;
        cudaGetSymbolAddress(&p, g_h);       p_h   = (__half*)p;
        cudaGetSymbolAddress(&p, g_xl2);     p_xl2 = (__half*)p;
        cudaGetSymbolAddress(&p, g_xr2);     p_xr2 = (float*)p;
        cudaGetSymbolAddress(&p, g_deg);     p_deg = (int*)p;
        cudaGetSymbolAddress(&p, g_off);     p_off = (int*)p;
        cudaGetSymbolAddress(&p, g_cur);     p_cur = (int*)p;
        cudaGetSymbolAddress(&p, g_bsum);    p_bsum = (int*)p;
        cudaGetSymbolAddress(&p, g_csr_src); p_csr = (int*)p;
        cudaStreamCreateWithFlags(&s_side, cudaStreamNonBlocking);
        cudaEventCreateWithFlags(&s_fork, cudaEventDisableTiming);
        cudaEventCreateWithFlags(&s_join, cudaEventDisableTiming);
    }

    const float* x     = (const float*)d_in[0];
    const int*   ei    = (const int*)d_in[1];
    const float* Wl1   = (const float*)d_in[2];
    const float* bl1   = (const float*)d_in[3];
    const float* Wr1   = (const float*)d_in[4];
    const float* br1   = (const float*)d_in[5];
    const float* att1  = (const float*)d_in[6];
    const float* bias1 = (const float*)d_in[7];
    const float* Wl2   = (const float*)d_in[8];
    const float* bl2   = (const float*)d_in[9];
    const float* Wr2   = (const float*)d_in[10];
    const float* br2   = (const float*)d_in[11];
    const float* att2  = (const float*)d_in[12];
    const float* bias2 = (const float*)d_in[13];
    float* out = (float*)d_out;

    const int IN = 128;
    const int N  = in_sizes[0] / IN;
    const int E  = in_sizes[1] / 2;
    const int TE = E + N;

    const int T = 256;
    auto cdiv = [](int a, int b) { return (a + b - 1) / b; };
    int nb = cdiv(N, 1024);

    // ---- fork event first so side-stream CSR overlaps converts + gemm1 ----
    cudaEventRecord(s_fork, 0);
    cudaStreamWaitEvent(s_side, s_fork, 0);

    // ---- main: fp16 pre-conversion ----
    cvt_f2h<<<cdiv(N * IN / 8, T), T>>>(x, p_xh, N * IN);
    cvt_wcat<<<cdiv(128 * 512, T), T>>>(Wl1, Wr1, p_w1h, 128, kHC1, kHC1);
    cvt_wcat<<<cdiv(256 * 128, T), T>>>(Wl2, Wr2, p_w2h, 256, kC2, kC2);

    // ---- layer 1 GEMM (launch 4: ncu window) ----
    {
        dim3 grid((kHC1 + kHC1) / 128, cdiv(N, 128));
        gemm_dual_tc<true><<<grid, 256>>>(p_xh, p_w1h, bl1, (void*)p_xl1, kHC1,
                                          br1, p_xr1, kHC1, N, IN);
    }

    // ---- side: CSR build, overlapped ----
    count_deg<<<cdiv(TE, T), T, 0, s_side>>>(ei, E, TE, p_deg);
    scan_block<<<nb, 1024, 0, s_side>>>(p_deg, p_off, p_bsum, N);
    scan_add2<<<cdiv(N, T), T, 0, s_side>>>(p_off, p_bsum, p_cur, N, TE, nb);
    scatter_csr<<<cdiv(TE, T), T, 0, s_side>>>(ei, E, TE, p_cur, p_csr);
    cudaEventRecord(s_join, s_side);

    // ---- join, then fused edge phase layer 1 -> h (fp16) ----
    cudaStreamWaitEvent(0, s_join, 0);
    gat_fused_l1<<<cdiv(N * 32, T), T>>>(p_off, p_csr, p_xl1, p_xr1, att1, bias1, p_h, N);

    // ---- layer 2 GEMM ----
    {
        dim3 grid((kC2 + kC2) / 128, cdiv(N, 128));
        gemm_dual_tc<true><<<grid, 256>>>(p_h, p_w2h, bl2, (void*)p_xl2, kC2,
                                          br2, p_xr2, kC2, N, kHC1);
    }
    // ---- layer 2 fused edge phase -> out ----
    gat_fused_l2<<<cdiv(N * 32, T), T>>>(p_off, p_csr, p_xl2, p_xr2, att2, bias2, out, N);

    // ---- re-zero deg for the next replay ----
    zeroi<<<cdiv(N, T), T>>>(p_deg, N);
}